// round 1
// baseline (speedup 1.0000x reference)
#include <cuda_runtime.h>
#include <math.h>

#define S_LEN   1024
#define D_MODEL 768
#define DI_     1536
#define N_ST    16
#define K_CONV  4
#define DTRANK  48
#define XD      80      // DTRANK + 2*N_ST
#define VOCAB   32000
#define NL_     2

// ---------------- scratch (static device globals; no allocation) ----------------
__device__ __align__(128) float g_x   [S_LEN * D_MODEL];   // residual stream
__device__ __align__(128) float g_xz  [S_LEN * 2 * DI_];   // in-proj output
__device__ __align__(128) float g_xs  [S_LEN * DI_];       // post conv+silu
__device__ __align__(128) float g_xdbl[S_LEN * XD];        // dt_low | B | C
__device__ __align__(128) float g_dt  [S_LEN * DI_];
__device__ __align__(128) float g_y   [S_LEN * DI_];
__device__ __align__(128) float g_tmp [S_LEN * D_MODEL];

// ---------------- helpers ----------------
__device__ __forceinline__ float silu_f(float x) {
    return x / (1.0f + __expf(-x));
}

// ---------------- embedding ----------------
__global__ void embed_kernel(const int* __restrict__ tokens,
                             const float* __restrict__ emb) {
    int i = blockIdx.x * blockDim.x + threadIdx.x;
    if (i < S_LEN * D_MODEL) {
        int l = i / D_MODEL, d = i - l * D_MODEL;
        g_x[i] = emb[(size_t)tokens[l] * D_MODEL + d];
    }
}

// ---------------- generic SGEMM: C[M,N] = A[M,K] * B[N,K]^T ----------------
// Both A and B are K-contiguous (row-major). M%128==0, N%128==0, K%8==0.
__global__ __launch_bounds__(256)
void sgemm_nt(const float* __restrict__ A, const float* __restrict__ B,
              float* __restrict__ C, int M, int N, int K) {
    __shared__ float As[8][128];
    __shared__ float Bs[8][128];

    const int tid = threadIdx.x;
    const int bm = blockIdx.y * 128;
    const int bn = blockIdx.x * 128;

    // load mapping: 256 threads * float4 = 1024 floats = 128x8 tile
    const int lrow = tid >> 1;            // 0..127
    const int lcol = (tid & 1) * 4;       // 0 or 4

    const int tx = tid & 15;              // 0..15
    const int ty = tid >> 4;              // 0..15

    float acc[8][8];
#pragma unroll
    for (int i = 0; i < 8; i++)
#pragma unroll
        for (int j = 0; j < 8; j++) acc[i][j] = 0.0f;

    for (int k0 = 0; k0 < K; k0 += 8) {
        float4 av = *(const float4*)(A + (size_t)(bm + lrow) * K + k0 + lcol);
        float4 bv = *(const float4*)(B + (size_t)(bn + lrow) * K + k0 + lcol);
        As[lcol + 0][lrow] = av.x;
        As[lcol + 1][lrow] = av.y;
        As[lcol + 2][lrow] = av.z;
        As[lcol + 3][lrow] = av.w;
        Bs[lcol + 0][lrow] = bv.x;
        Bs[lcol + 1][lrow] = bv.y;
        Bs[lcol + 2][lrow] = bv.z;
        Bs[lcol + 3][lrow] = bv.w;
        __syncthreads();

#pragma unroll
        for (int k = 0; k < 8; k++) {
            float ar[8], br[8];
#pragma unroll
            for (int i = 0; i < 8; i++) ar[i] = As[k][ty * 8 + i];
#pragma unroll
            for (int j = 0; j < 8; j++) br[j] = Bs[k][tx * 8 + j];
#pragma unroll
            for (int i = 0; i < 8; i++)
#pragma unroll
                for (int j = 0; j < 8; j++) acc[i][j] += ar[i] * br[j];
        }
        __syncthreads();
    }

#pragma unroll
    for (int i = 0; i < 8; i++) {
        size_t row = (size_t)(bm + ty * 8 + i) * N + bn + tx * 8;
        float4 v0 = make_float4(acc[i][0], acc[i][1], acc[i][2], acc[i][3]);
        float4 v1 = make_float4(acc[i][4], acc[i][5], acc[i][6], acc[i][7]);
        *(float4*)(C + row)     = v0;
        *(float4*)(C + row + 4) = v1;
    }
}

// ---------------- causal depthwise conv1d + bias + silu ----------------
__global__ void conv_silu_kernel(const float* __restrict__ conv_w,
                                 const float* __restrict__ conv_b, int layer) {
    int i = blockIdx.x * blockDim.x + threadIdx.x;
    if (i >= S_LEN * DI_) return;
    int t = i / DI_, c = i - t * DI_;
    const float* w = conv_w + ((size_t)layer * DI_ + c) * K_CONV;
    float acc = conv_b[layer * DI_ + c];
#pragma unroll
    for (int k = 0; k < K_CONV; k++) {
        int tt = t - (K_CONV - 1) + k;
        if (tt >= 0) acc += w[k] * g_xz[(size_t)tt * 2 * DI_ + c];
    }
    g_xs[i] = silu_f(acc);
}

// ---------------- x-projection: xdbl[l, 0..79] = xs[l,:] @ xproj_w^T ----------------
__global__ void xproj_kernel(const float* __restrict__ xproj_w, int layer) {
    int i = blockIdx.x * blockDim.x + threadIdx.x;
    if (i >= S_LEN * XD) return;
    int l = i / XD, j = i - l * XD;
    const float4* xrow = (const float4*)(g_xs + (size_t)l * DI_);
    const float4* wrow = (const float4*)(xproj_w + ((size_t)layer * XD + j) * DI_);
    float acc = 0.0f;
#pragma unroll 4
    for (int k = 0; k < DI_ / 4; k++) {
        float4 a = xrow[k], b = wrow[k];
        acc += a.x * b.x + a.y * b.y + a.z * b.z + a.w * b.w;
    }
    g_xdbl[i] = acc;
}

// ---------------- dt = softplus(xdbl[:, :48] @ dt_w^T + dt_b) ----------------
__global__ void dt_kernel(const float* __restrict__ dt_w,
                          const float* __restrict__ dt_b, int layer) {
    __shared__ float sh[DTRANK];
    int l = blockIdx.y;
    int c = blockIdx.x * 256 + threadIdx.x;
    if (threadIdx.x < DTRANK) sh[threadIdx.x] = g_xdbl[(size_t)l * XD + threadIdx.x];
    __syncthreads();
    float acc = dt_b[layer * DI_ + c];
    const float* w = dt_w + ((size_t)layer * DI_ + c) * DTRANK;
#pragma unroll
    for (int r = 0; r < DTRANK; r++) acc += sh[r] * w[r];
    float sp = (acc > 20.0f) ? acc : log1pf(expf(acc));
    g_dt[(size_t)l * DI_ + c] = sp;
}

// ---------------- selective scan ----------------
// one 16-lane group per channel; each lane owns state n; sequential over t.
__global__ __launch_bounds__(256)
void scan_kernel(const float* __restrict__ A_log, int layer) {
    int n  = threadIdx.x & 15;
    int cl = threadIdx.x >> 4;           // 0..15
    int c  = blockIdx.x * 16 + cl;
    float Acn = -expf(A_log[((size_t)layer * DI_ + c) * N_ST + n]);
    float h = 0.0f;
    for (int t = 0; t < S_LEN; t++) {
        float dtv = g_dt[(size_t)t * DI_ + c];
        float xv  = g_xs[(size_t)t * DI_ + c];
        float Bv  = g_xdbl[(size_t)t * XD + DTRANK + n];
        float Cv  = g_xdbl[(size_t)t * XD + DTRANK + N_ST + n];
        h = __expf(dtv * Acn) * h + dtv * Bv * xv;
        float v = h * Cv;
#pragma unroll
        for (int o = 8; o > 0; o >>= 1)
            v += __shfl_down_sync(0xffffffffu, v, o, 16);
        if (n == 0) g_y[(size_t)t * DI_ + c] = v;
    }
}

// ---------------- gate: y = (y + xs*Dp) * silu(z) ----------------
__global__ void gate_kernel(const float* __restrict__ Dp, int layer) {
    int i = blockIdx.x * blockDim.x + threadIdx.x;
    if (i >= S_LEN * DI_) return;
    int t = i / DI_, c = i - t * DI_;
    float z = g_xz[(size_t)t * 2 * DI_ + DI_ + c];
    g_y[i] = (g_y[i] + g_xs[i] * Dp[layer * DI_ + c]) * silu_f(z);
}

// ---------------- residual + layernorm ----------------
__global__ __launch_bounds__(256)
void ln_kernel(const float* __restrict__ gam, const float* __restrict__ bet, int layer) {
    int l = blockIdx.x;
    __shared__ float rsum[8], rsq[8];
    float sum = 0.0f, sq = 0.0f;
    for (int d = threadIdx.x; d < D_MODEL; d += 256) {
        float v = g_x[(size_t)l * D_MODEL + d] + g_tmp[(size_t)l * D_MODEL + d];
        sum += v; sq += v * v;
    }
#pragma unroll
    for (int o = 16; o > 0; o >>= 1) {
        sum += __shfl_down_sync(0xffffffffu, sum, o);
        sq  += __shfl_down_sync(0xffffffffu, sq, o);
    }
    int wid = threadIdx.x >> 5;
    if ((threadIdx.x & 31) == 0) { rsum[wid] = sum; rsq[wid] = sq; }
    __syncthreads();
    if (threadIdx.x == 0) {
        float s = 0.0f, q = 0.0f;
#pragma unroll
        for (int w = 0; w < 8; w++) { s += rsum[w]; q += rsq[w]; }
        rsum[0] = s; rsq[0] = q;
    }
    __syncthreads();
    float mu  = rsum[0] / (float)D_MODEL;
    float var = rsq[0] / (float)D_MODEL - mu * mu;
    float rinv = rsqrtf(var + 1e-5f);
    for (int d = threadIdx.x; d < D_MODEL; d += 256) {
        float v = g_x[(size_t)l * D_MODEL + d] + g_tmp[(size_t)l * D_MODEL + d];
        g_x[(size_t)l * D_MODEL + d] =
            (v - mu) * rinv * gam[layer * D_MODEL + d] + bet[layer * D_MODEL + d];
    }
}

// ---------------- launch ----------------
extern "C" void kernel_launch(void* const* d_in, const int* in_sizes, int n_in,
                              void* d_out, int out_size) {
    const int*   tokens  = (const int*)  d_in[0];
    const float* emb     = (const float*)d_in[1];
    const float* in_w    = (const float*)d_in[2];
    const float* conv_w  = (const float*)d_in[3];
    const float* conv_b  = (const float*)d_in[4];
    const float* xproj_w = (const float*)d_in[5];
    const float* dt_w    = (const float*)d_in[6];
    const float* dt_b    = (const float*)d_in[7];
    const float* A_log   = (const float*)d_in[8];
    const float* Dp      = (const float*)d_in[9];
    const float* out_w   = (const float*)d_in[10];
    const float* ln_g    = (const float*)d_in[11];
    const float* ln_b    = (const float*)d_in[12];
    const float* head_w  = (const float*)d_in[13];
    float* out = (float*)d_out;

    static float *px = nullptr, *pxz = nullptr, *py = nullptr, *ptmp = nullptr;
    if (!px) {
        cudaGetSymbolAddress((void**)&px,   g_x);
        cudaGetSymbolAddress((void**)&pxz,  g_xz);
        cudaGetSymbolAddress((void**)&py,   g_y);
        cudaGetSymbolAddress((void**)&ptmp, g_tmp);
    }

    embed_kernel<<<(S_LEN * D_MODEL + 255) / 256, 256>>>(tokens, emb);

    for (int L = 0; L < NL_; L++) {
        // in-proj: [1024,768] x [3072,768]^T -> [1024,3072]
        sgemm_nt<<<dim3(2 * DI_ / 128, S_LEN / 128), 256>>>(
            px, in_w + (size_t)L * 2 * DI_ * D_MODEL, pxz, S_LEN, 2 * DI_, D_MODEL);
        conv_silu_kernel<<<(S_LEN * DI_ + 255) / 256, 256>>>(conv_w, conv_b, L);
        xproj_kernel<<<(S_LEN * XD + 255) / 256, 256>>>(xproj_w, L);
        dt_kernel<<<dim3(DI_ / 256, S_LEN), 256>>>(dt_w, dt_b, L);
        scan_kernel<<<DI_ / 16, 256>>>(A_log, L);
        gate_kernel<<<(S_LEN * DI_ + 255) / 256, 256>>>(Dp, L);
        // out-proj: [1024,1536] x [768,1536]^T -> [1024,768]
        sgemm_nt<<<dim3(D_MODEL / 128, S_LEN / 128), 256>>>(
            py, out_w + (size_t)L * D_MODEL * DI_, ptmp, S_LEN, D_MODEL, DI_);
        ln_kernel<<<S_LEN, 256>>>(ln_g, ln_b, L);
    }

    // head: [1024,768] x [32000,768]^T -> [1024,32000]
    sgemm_nt<<<dim3(VOCAB / 128, S_LEN / 128), 256>>>(
        px, head_w, out, S_LEN, VOCAB, D_MODEL);
}

// round 3
// speedup vs baseline: 1.6545x; 1.6545x over previous
#include <cuda_runtime.h>
#include <cstdint>
#include <math.h>

#define S_LEN   1024
#define D_MODEL 768
#define DI_     1536
#define N_ST    16
#define K_CONV  4
#define DTRANK  48
#define XDP     256     // padded x_dbl pitch (dt 0..47 | B 48..63 | C 64..79 | zeros)
#define VOCAB   32000
#define NL_     2

// ---------------- scratch ----------------
__device__ __align__(128) float g_x     [S_LEN * D_MODEL];
__device__ __align__(128) float g_xz    [S_LEN * 2 * DI_];
__device__ __align__(128) float g_xs    [S_LEN * DI_];
__device__ __align__(128) float g_xdbl  [S_LEN * XDP];
__device__ __align__(128) float g_dtl   [S_LEN * DI_];
__device__ __align__(128) float g_y     [S_LEN * DI_];
__device__ __align__(128) float g_tmp   [S_LEN * D_MODEL];
__device__ __align__(128) float g_wpad  [256 * DI_];     // padded xproj_w
__device__ __align__(128) float g_dtwpad[DI_ * 64];      // padded dt_w

// ---------------- PTX helpers ----------------
__device__ __forceinline__ uint32_t smem_u32(const void* p) {
    uint32_t a;
    asm("{ .reg .u64 t; cvta.to.shared.u64 t, %1; cvt.u32.u64 %0, t; }" : "=r"(a) : "l"(p));
    return a;
}

#define CP_ASYNC16(dst, src) \
    asm volatile("cp.async.cg.shared.global [%0], [%1], 16;" :: "r"(dst), "l"(src))
#define CP_COMMIT() asm volatile("cp.async.commit_group;" ::: "memory")
#define CP_WAIT(n)  asm volatile("cp.async.wait_group %0;" :: "n"(n) : "memory")

// load fp32 from swizzled smem (row r of 32 floats, col c), round to tf32
__device__ __forceinline__ uint32_t ldtf(uint32_t base, int r, int c) {
    uint32_t off = ((uint32_t)r << 7) | (((uint32_t)c << 2) ^ (((uint32_t)(r & 7)) << 4));
    float v;
    asm volatile("ld.shared.f32 %0, [%1];" : "=f"(v) : "r"(base + off));
    uint32_t t;
    asm volatile("cvt.rna.tf32.f32 %0, %1;" : "=r"(t) : "f"(v));
    return t;
}

__device__ __forceinline__ void mma_tf32(float* c, const uint32_t* a, const uint32_t* b) {
    asm volatile(
        "mma.sync.aligned.m16n8k8.row.col.f32.tf32.tf32.f32 "
        "{%0,%1,%2,%3}, {%4,%5,%6,%7}, {%8,%9}, {%0,%1,%2,%3};"
        : "+f"(c[0]), "+f"(c[1]), "+f"(c[2]), "+f"(c[3])
        : "r"(a[0]), "r"(a[1]), "r"(a[2]), "r"(a[3]), "r"(b[0]), "r"(b[1]));
}

// ---------------- tf32 mma.sync GEMM: C[M,N] = A[M,K] * B[N,K]^T ----------------
// grid = (M/BM, N/BN), block = 256 (8 warps, (BM/WM)x(BN/WN) layout).
// K % 32 == 0. A,B row-major K-contiguous fp32.
template<int BM, int BN, int WM, int WN>
__global__ __launch_bounds__(256)
void gemm_mma(const float* __restrict__ A, const float* __restrict__ B,
              float* __restrict__ C, int K, int lda, int ldb, int ldc)
{
    extern __shared__ float smem[];
    constexpr int ASTG = BM * 32;            // floats per A stage
    constexpr int BSTG = BN * 32;            // floats per B stage
    constexpr int MF = WM / 16, NF = WN / 8;
    constexpr int WCOLS = BN / WN;

    const int tid = threadIdx.x, lane = tid & 31, wid = tid >> 5;
    const int wm = wid / WCOLS, wn = wid % WCOLS;
    const int bm = blockIdx.x * BM, bn = blockIdx.y * BN;
    const int nc = K >> 5;

    const uint32_t sb = smem_u32(smem);
    const float* Ab = A + (size_t)bm * lda;
    const float* Bb = B + (size_t)bn * ldb;

    auto loadA = [&](int chunk, int st) {
        uint32_t d0 = sb + st * (ASTG * 4);
        const float* s0 = Ab + chunk * 32;
#pragma unroll
        for (int it = 0; it < BM / 32; it++) {
            int i = tid + it * 256;
            int r = i >> 3, q = i & 7;
            uint32_t off = ((uint32_t)r << 7) | (((uint32_t)q << 4) ^ (((uint32_t)(r & 7)) << 4));
            CP_ASYNC16(d0 + off, s0 + (size_t)r * lda + q * 4);
        }
    };
    auto loadB = [&](int chunk, int st) {
        uint32_t d0 = sb + (3 * ASTG + st * BSTG) * 4;
        const float* s0 = Bb + chunk * 32;
#pragma unroll
        for (int it = 0; it < BN / 32; it++) {
            int i = tid + it * 256;
            int r = i >> 3, q = i & 7;
            uint32_t off = ((uint32_t)r << 7) | (((uint32_t)q << 4) ^ (((uint32_t)(r & 7)) << 4));
            CP_ASYNC16(d0 + off, s0 + (size_t)r * ldb + q * 4);
        }
    };

    float acc[MF][NF][4];
#pragma unroll
    for (int i = 0; i < MF; i++)
#pragma unroll
        for (int j = 0; j < NF; j++)
#pragma unroll
            for (int v = 0; v < 4; v++) acc[i][j][v] = 0.0f;

    int npre = nc < 2 ? nc : 2;
    for (int c = 0; c < npre; c++) { loadA(c, c); loadB(c, c); CP_COMMIT(); }

    for (int i = 0; i < nc; i++) {
        if (i + 2 < nc) { CP_WAIT(1); } else { CP_WAIT(0); }
        __syncthreads();
        if (i + 2 < nc) {
            int s2 = (i + 2) % 3;
            loadA(i + 2, s2); loadB(i + 2, s2); CP_COMMIT();
        }
        uint32_t abase = sb + (i % 3) * (ASTG * 4);
        uint32_t bbase = sb + (3 * ASTG + (i % 3) * BSTG) * 4;
#pragma unroll
        for (int ks = 0; ks < 4; ks++) {
            int k0 = ks * 8;
            int cc = k0 + (lane & 3);
            uint32_t afr[MF][4];
#pragma unroll
            for (int mf = 0; mf < MF; mf++) {
                int r = wm * WM + mf * 16 + (lane >> 2);
                afr[mf][0] = ldtf(abase, r,     cc);
                afr[mf][1] = ldtf(abase, r + 8, cc);
                afr[mf][2] = ldtf(abase, r,     cc + 4);
                afr[mf][3] = ldtf(abase, r + 8, cc + 4);
            }
            uint32_t bfr[NF][2];
#pragma unroll
            for (int nf = 0; nf < NF; nf++) {
                int n = wn * WN + nf * 8 + (lane >> 2);
                bfr[nf][0] = ldtf(bbase, n, cc);
                bfr[nf][1] = ldtf(bbase, n, cc + 4);
            }
#pragma unroll
            for (int mf = 0; mf < MF; mf++)
#pragma unroll
                for (int nf = 0; nf < NF; nf++)
                    mma_tf32(acc[mf][nf], afr[mf], bfr[nf]);
        }
    }

#pragma unroll
    for (int mf = 0; mf < MF; mf++) {
        int row = bm + wm * WM + mf * 16 + (lane >> 2);
#pragma unroll
        for (int nf = 0; nf < NF; nf++) {
            int col = bn + wn * WN + nf * 8 + 2 * (lane & 3);
            *(float2*)(C + (size_t)row * ldc + col) =
                make_float2(acc[mf][nf][0], acc[mf][nf][1]);
            *(float2*)(C + (size_t)(row + 8) * ldc + col) =
                make_float2(acc[mf][nf][2], acc[mf][nf][3]);
        }
    }
}

#define SMEM_BIG   (3 * (128 * 32 + 256 * 32) * 4)   // 147456
#define SMEM_SMALL (3 * (128 * 32 + 128 * 32) * 4)   // 98304

// ---------------- small kernels ----------------
__device__ __forceinline__ float silu_f(float x) { return x / (1.0f + __expf(-x)); }

__global__ void embed_kernel(const int* __restrict__ tokens,
                             const float* __restrict__ emb) {
    int i = blockIdx.x * blockDim.x + threadIdx.x;
    if (i < S_LEN * D_MODEL) {
        int l = i / D_MODEL, d = i - l * D_MODEL;
        g_x[i] = emb[(size_t)tokens[l] * D_MODEL + d];
    }
}

__global__ void padw_kernel(const float* __restrict__ xw, int L) {
    int i = blockIdx.x * 256 + threadIdx.x;
    if (i >= 256 * DI_) return;
    int row = i / DI_, col = i - row * DI_;
    g_wpad[i] = (row < 80) ? xw[((size_t)L * 80 + row) * DI_ + col] : 0.0f;
}

__global__ void paddt_kernel(const float* __restrict__ dw, int L) {
    int i = blockIdx.x * 256 + threadIdx.x;
    if (i >= DI_ * 64) return;
    int row = i >> 6, col = i & 63;
    g_dtwpad[i] = (col < DTRANK) ? dw[((size_t)L * DI_ + row) * DTRANK + col] : 0.0f;
}

__global__ void conv_silu_kernel(const float* __restrict__ conv_w,
                                 const float* __restrict__ conv_b, int layer) {
    int i = blockIdx.x * blockDim.x + threadIdx.x;
    if (i >= S_LEN * DI_) return;
    int t = i / DI_, c = i - t * DI_;
    const float* w = conv_w + ((size_t)layer * DI_ + c) * K_CONV;
    float acc = conv_b[layer * DI_ + c];
#pragma unroll
    for (int k = 0; k < K_CONV; k++) {
        int tt = t - (K_CONV - 1) + k;
        if (tt >= 0) acc += w[k] * g_xz[(size_t)tt * 2 * DI_ + c];
    }
    g_xs[i] = silu_f(acc);
}

// scan + fused softplus(dt) + gate
__global__ __launch_bounds__(256)
void scan_kernel(const float* __restrict__ A_log, const float* __restrict__ dt_b,
                 const float* __restrict__ Dp, int layer) {
    int n  = threadIdx.x & 15;
    int cl = threadIdx.x >> 4;
    int c  = blockIdx.x * 16 + cl;
    float Acn  = -expf(A_log[((size_t)layer * DI_ + c) * N_ST + n]);
    float bias = dt_b[layer * DI_ + c];
    float Dpc  = Dp[layer * DI_ + c];
    float h = 0.0f;
    for (int t = 0; t < S_LEN; t++) {
        float a   = g_dtl[(size_t)t * DI_ + c] + bias;
        float dtv = (a > 20.0f) ? a : log1pf(__expf(a));
        float xv  = g_xs[(size_t)t * DI_ + c];
        float Bv  = g_xdbl[(size_t)t * XDP + DTRANK + n];
        float Cv  = g_xdbl[(size_t)t * XDP + DTRANK + N_ST + n];
        h = __expf(dtv * Acn) * h + dtv * Bv * xv;
        float v = h * Cv;
#pragma unroll
        for (int o = 8; o > 0; o >>= 1)
            v += __shfl_down_sync(0xffffffffu, v, o, 16);
        if (n == 0) {
            float z = g_xz[(size_t)t * 2 * DI_ + DI_ + c];
            g_y[(size_t)t * DI_ + c] = (v + xv * Dpc) * silu_f(z);
        }
    }
}

__global__ __launch_bounds__(256)
void ln_kernel(const float* __restrict__ gam, const float* __restrict__ bet, int layer) {
    int l = blockIdx.x;
    __shared__ float rsum[8], rsq[8];
    float sum = 0.0f, sq = 0.0f;
    for (int d = threadIdx.x; d < D_MODEL; d += 256) {
        float v = g_x[(size_t)l * D_MODEL + d] + g_tmp[(size_t)l * D_MODEL + d];
        sum += v; sq += v * v;
    }
#pragma unroll
    for (int o = 16; o > 0; o >>= 1) {
        sum += __shfl_down_sync(0xffffffffu, sum, o);
        sq  += __shfl_down_sync(0xffffffffu, sq, o);
    }
    int wid = threadIdx.x >> 5;
    if ((threadIdx.x & 31) == 0) { rsum[wid] = sum; rsq[wid] = sq; }
    __syncthreads();
    if (threadIdx.x == 0) {
        float s = 0.0f, q = 0.0f;
#pragma unroll
        for (int w = 0; w < 8; w++) { s += rsum[w]; q += rsq[w]; }
        rsum[0] = s; rsq[0] = q;
    }
    __syncthreads();
    float mu  = rsum[0] / (float)D_MODEL;
    float var = rsq[0] / (float)D_MODEL - mu * mu;
    float rinv = rsqrtf(var + 1e-5f);
    for (int d = threadIdx.x; d < D_MODEL; d += 256) {
        float v = g_x[(size_t)l * D_MODEL + d] + g_tmp[(size_t)l * D_MODEL + d];
        g_x[(size_t)l * D_MODEL + d] =
            (v - mu) * rinv * gam[layer * D_MODEL + d] + bet[layer * D_MODEL + d];
    }
}

// ---------------- launch ----------------
extern "C" void kernel_launch(void* const* d_in, const int* in_sizes, int n_in,
                              void* d_out, int out_size) {
    const int*   tokens  = (const int*)  d_in[0];
    const float* emb     = (const float*)d_in[1];
    const float* in_w    = (const float*)d_in[2];
    const float* conv_w  = (const float*)d_in[3];
    const float* conv_b  = (const float*)d_in[4];
    const float* xproj_w = (const float*)d_in[5];
    const float* dt_w    = (const float*)d_in[6];
    const float* dt_b    = (const float*)d_in[7];
    const float* A_log   = (const float*)d_in[8];
    const float* Dp      = (const float*)d_in[9];
    const float* out_w   = (const float*)d_in[10];
    const float* ln_g    = (const float*)d_in[11];
    const float* ln_b    = (const float*)d_in[12];
    const float* head_w  = (const float*)d_in[13];
    float* out = (float*)d_out;

    static float *px = nullptr, *pxz, *pxs, *pxdbl, *pdtl, *py, *ptmp, *pwpad, *pdtw;
    if (!px) {
        cudaGetSymbolAddress((void**)&pxz,   g_xz);
        cudaGetSymbolAddress((void**)&pxs,   g_xs);
        cudaGetSymbolAddress((void**)&pxdbl, g_xdbl);
        cudaGetSymbolAddress((void**)&pdtl,  g_dtl);
        cudaGetSymbolAddress((void**)&py,    g_y);
        cudaGetSymbolAddress((void**)&ptmp,  g_tmp);
        cudaGetSymbolAddress((void**)&pwpad, g_wpad);
        cudaGetSymbolAddress((void**)&pdtw,  g_dtwpad);
        cudaFuncSetAttribute(gemm_mma<128, 256, 64, 64>,
                             cudaFuncAttributeMaxDynamicSharedMemorySize, SMEM_BIG);
        cudaFuncSetAttribute(gemm_mma<128, 128, 64, 32>,
                             cudaFuncAttributeMaxDynamicSharedMemorySize, SMEM_SMALL);
        cudaGetSymbolAddress((void**)&px,    g_x);
    }

    embed_kernel<<<(S_LEN * D_MODEL + 255) / 256, 256>>>(tokens, emb);

    for (int L = 0; L < NL_; L++) {
        padw_kernel<<<(256 * DI_ + 255) / 256, 256>>>(xproj_w, L);
        paddt_kernel<<<(DI_ * 64 + 255) / 256, 256>>>(dt_w, L);

        // in-proj: [1024,768] x [3072,768]^T -> g_xz [1024,3072]
        gemm_mma<128, 256, 64, 64><<<dim3(S_LEN / 128, 2 * DI_ / 256), 256, SMEM_BIG>>>(
            px, in_w + (size_t)L * 2 * DI_ * D_MODEL, pxz, D_MODEL, D_MODEL, D_MODEL, 2 * DI_);
        conv_silu_kernel<<<(S_LEN * DI_ + 255) / 256, 256>>>(conv_w, conv_b, L);

        // x-proj (padded to 256 outs): [1024,1536] x [256,1536]^T -> g_xdbl [1024,256]
        gemm_mma<128, 128, 64, 32><<<dim3(S_LEN / 128, XDP / 128), 256, SMEM_SMALL>>>(
            pxs, pwpad, pxdbl, DI_, DI_, DI_, XDP);

        // dt-proj (K padded 48->64): [1024,64] x [1536,64]^T -> g_dtl [1024,1536]
        gemm_mma<128, 128, 64, 32><<<dim3(S_LEN / 128, DI_ / 128), 256, SMEM_SMALL>>>(
            pxdbl, pdtw, pdtl, 64, XDP, 64, DI_);

        scan_kernel<<<DI_ / 16, 256>>>(A_log, dt_b, Dp, L);

        // out-proj: [1024,1536] x [768,1536]^T -> g_tmp [1024,768]
        gemm_mma<128, 128, 64, 32><<<dim3(S_LEN / 128, D_MODEL / 128), 256, SMEM_SMALL>>>(
            py, out_w + (size_t)L * D_MODEL * DI_, ptmp, DI_, DI_, DI_, D_MODEL);

        ln_kernel<<<S_LEN, 256>>>(ln_g, ln_b, L);
    }

    // head: [1024,768] x [32000,768]^T -> out [1024,32000]
    gemm_mma<128, 256, 64, 64><<<dim3(S_LEN / 128, VOCAB / 256), 256, SMEM_BIG>>>(
        px, head_w, out, D_MODEL, D_MODEL, D_MODEL, VOCAB);
}

// round 4
// speedup vs baseline: 3.5198x; 2.1274x over previous
#include <cuda_runtime.h>
#include <cstdint>
#include <math.h>

#define S_LEN   1024
#define D_MODEL 768
#define DI_     1536
#define N_ST    16
#define K_CONV  4
#define DTRANK  48
#define XDP     256
#define VOCAB   32000
#define NL_     2
#define NCHUNK  8
#define CLEN    128     // S_LEN / NCHUNK
#define GROUPS  (DI_ * N_ST)   // 24576

// ---------------- scratch ----------------
__device__ __align__(128) float g_x     [S_LEN * D_MODEL];
__device__ __align__(128) float g_xz    [S_LEN * 2 * DI_];
__device__ __align__(128) float g_xs    [S_LEN * DI_];
__device__ __align__(128) float g_xdbl  [S_LEN * XDP];
__device__ __align__(128) float g_dtl   [S_LEN * DI_];
__device__ __align__(128) float g_y     [S_LEN * DI_];
__device__ __align__(128) float g_tmp   [S_LEN * D_MODEL];
__device__ __align__(128) float g_wpad  [256 * DI_];
__device__ __align__(128) float g_dtwpad[DI_ * 64];
__device__ __align__(128) float g_wbig  [2 * DI_ * D_MODEL];  // rounded in_w slice
__device__ __align__(128) float g_wout  [D_MODEL * DI_];      // rounded out_w slice
__device__ __align__(128) float g_wh    [VOCAB * D_MODEL];    // rounded head_w
__device__ __align__(128) float g_P     [NCHUNK * GROUPS];
__device__ __align__(128) float g_H     [NCHUNK * GROUPS];
__device__ __align__(128) float g_C0    [NCHUNK * GROUPS];

// ---------------- helpers ----------------
__device__ __forceinline__ uint32_t smem_u32(const void* p) {
    uint32_t a;
    asm("{ .reg .u64 t; cvta.to.shared.u64 t, %1; cvt.u32.u64 %0, t; }" : "=r"(a) : "l"(p));
    return a;
}
__device__ __forceinline__ float rna_tf32(float v) {
    uint32_t t;
    asm("cvt.rna.tf32.f32 %0, %1;" : "=r"(t) : "f"(v));
    return __uint_as_float(t);
}
__device__ __forceinline__ float silu_f(float x) { return x / (1.0f + __expf(-x)); }

#define CP_ASYNC16(dst, src) \
    asm volatile("cp.async.cg.shared.global [%0], [%1], 16;" :: "r"(dst), "l"(src))
#define CP_COMMIT() asm volatile("cp.async.commit_group;" ::: "memory")
#define CP_WAIT(n)  asm volatile("cp.async.wait_group %0;" :: "n"(n) : "memory")
#define LDSM4(d0, d1, d2, d3, a) \
    asm volatile("ldmatrix.sync.aligned.m8n8.x4.shared.b16 {%0,%1,%2,%3}, [%4];" \
        : "=r"(d0), "=r"(d1), "=r"(d2), "=r"(d3) : "r"(a))

__device__ __forceinline__ void mma_tf32(float* c, const uint32_t* a, const uint32_t* b) {
    asm volatile(
        "mma.sync.aligned.m16n8k8.row.col.f32.tf32.tf32.f32 "
        "{%0,%1,%2,%3}, {%4,%5,%6,%7}, {%8,%9}, {%0,%1,%2,%3};"
        : "+f"(c[0]), "+f"(c[1]), "+f"(c[2]), "+f"(c[3])
        : "r"(a[0]), "r"(a[1]), "r"(a[2]), "r"(a[3]), "r"(b[0]), "r"(b[1]));
}

// ---------------- tf32 mma GEMM: C[M,N] = A[M,K] * B[N,K]^T ----------------
// Inputs must be pre-rounded to tf32. grid=(M/BM, N/BN), block=256.
template<int BM, int BN, int WM, int WN, bool RC>
__global__ __launch_bounds__(256)
void gemm_mma(const float* __restrict__ A, const float* __restrict__ B,
              float* __restrict__ C, int K, int lda, int ldb, int ldc)
{
    extern __shared__ float smem[];
    constexpr int ASTG = BM * 32;
    constexpr int BSTG = BN * 32;
    constexpr int MF = WM / 16, NF = WN / 8, NP = NF / 2;
    constexpr int WCOLS = BN / WN;

    const int tid = threadIdx.x, lane = tid & 31, wid = tid >> 5;
    const int wm = wid / WCOLS, wn = wid % WCOLS;
    const int bm = blockIdx.x * BM, bn = blockIdx.y * BN;
    const int nc = K >> 5;
    const int lr = lane & 7, lg = lane >> 3;

    const uint32_t sb = smem_u32(smem);
    const float* Ab = A + (size_t)bm * lda;
    const float* Bb = B + (size_t)bn * ldb;

    auto loadA = [&](int chunk, int st) {
        uint32_t d0 = sb + st * (ASTG * 4);
        const float* s0 = Ab + chunk * 32;
#pragma unroll
        for (int it = 0; it < BM / 32; it++) {
            int i = tid + it * 256;
            int r = i >> 3, q = i & 7;
            uint32_t off = ((uint32_t)r << 7) | (((uint32_t)q << 4) ^ (((uint32_t)(r & 7)) << 4));
            CP_ASYNC16(d0 + off, s0 + (size_t)r * lda + q * 4);
        }
    };
    auto loadB = [&](int chunk, int st) {
        uint32_t d0 = sb + (3 * ASTG + st * BSTG) * 4;
        const float* s0 = Bb + chunk * 32;
#pragma unroll
        for (int it = 0; it < BN / 32; it++) {
            int i = tid + it * 256;
            int r = i >> 3, q = i & 7;
            uint32_t off = ((uint32_t)r << 7) | (((uint32_t)q << 4) ^ (((uint32_t)(r & 7)) << 4));
            CP_ASYNC16(d0 + off, s0 + (size_t)r * ldb + q * 4);
        }
    };

    // ldmatrix lane-invariant address parts
    const int a_row0 = wm * WM + ((lg & 1) << 3) + lr;   // +8 if lg odd
    const int a_coff = (lg >> 1) << 2;                   // +4 cols if lg>=2
    const int b_row0 = wn * WN + ((lg & 2) << 2) + lr;   // +8 if lg&2
    const int b_coff = (lg & 1) << 2;                    // +4 cols if lg odd
    const uint32_t sw = (uint32_t)lr << 4;

    float acc[MF][NF][4];
#pragma unroll
    for (int i = 0; i < MF; i++)
#pragma unroll
        for (int j = 0; j < NF; j++)
#pragma unroll
            for (int v = 0; v < 4; v++) acc[i][j][v] = 0.0f;

    int npre = nc < 2 ? nc : 2;
    for (int c = 0; c < npre; c++) { loadA(c, c); loadB(c, c); CP_COMMIT(); }

    for (int i = 0; i < nc; i++) {
        if (i + 2 < nc) { CP_WAIT(1); } else { CP_WAIT(0); }
        __syncthreads();
        if (i + 2 < nc) {
            int s2 = (i + 2) % 3;
            loadA(i + 2, s2); loadB(i + 2, s2); CP_COMMIT();
        }
        uint32_t abase = sb + (i % 3) * (ASTG * 4);
        uint32_t bbase = sb + (3 * ASTG + (i % 3) * BSTG) * 4;
#pragma unroll
        for (int ks = 0; ks < 4; ks++) {
            const int k0 = ks * 8;
            uint32_t afr[MF][4];
#pragma unroll
            for (int mf = 0; mf < MF; mf++) {
                uint32_t ad = abase + (uint32_t)(a_row0 + mf * 16) * 128 +
                              ((((uint32_t)(k0 + a_coff)) << 2) ^ sw);
                LDSM4(afr[mf][0], afr[mf][1], afr[mf][2], afr[mf][3], ad);
            }
            uint32_t bfr[NF][2];
#pragma unroll
            for (int p = 0; p < NP; p++) {
                uint32_t bd = bbase + (uint32_t)(b_row0 + p * 16) * 128 +
                              ((((uint32_t)(k0 + b_coff)) << 2) ^ sw);
                LDSM4(bfr[2 * p][0], bfr[2 * p][1], bfr[2 * p + 1][0], bfr[2 * p + 1][1], bd);
            }
#pragma unroll
            for (int mf = 0; mf < MF; mf++)
#pragma unroll
                for (int nf = 0; nf < NF; nf++)
                    mma_tf32(acc[mf][nf], afr[mf], bfr[nf]);
        }
    }

#pragma unroll
    for (int mf = 0; mf < MF; mf++) {
        int row = bm + wm * WM + mf * 16 + (lane >> 2);
#pragma unroll
        for (int nf = 0; nf < NF; nf++) {
            int col = bn + wn * WN + nf * 8 + 2 * (lane & 3);
            float v0 = acc[mf][nf][0], v1 = acc[mf][nf][1];
            float v2 = acc[mf][nf][2], v3 = acc[mf][nf][3];
            if (RC) { v0 = rna_tf32(v0); v1 = rna_tf32(v1); v2 = rna_tf32(v2); v3 = rna_tf32(v3); }
            *(float2*)(C + (size_t)row * ldc + col)       = make_float2(v0, v1);
            *(float2*)(C + (size_t)(row + 8) * ldc + col) = make_float2(v2, v3);
        }
    }
}

#define SMEM_BIG   (3 * (128 * 32 + 256 * 32) * 4)
#define SMEM_SMALL (3 * (128 * 32 + 128 * 32) * 4)

// ---------------- elementwise / small kernels ----------------
__global__ void roundcopy4(float4* __restrict__ dst, const float4* __restrict__ src, int n4) {
    int i = blockIdx.x * blockDim.x + threadIdx.x;
    if (i < n4) {
        float4 v = src[i];
        v.x = rna_tf32(v.x); v.y = rna_tf32(v.y);
        v.z = rna_tf32(v.z); v.w = rna_tf32(v.w);
        dst[i] = v;
    }
}

__global__ void embed_kernel(const int* __restrict__ tokens,
                             const float* __restrict__ emb) {
    int i = blockIdx.x * blockDim.x + threadIdx.x;
    if (i < S_LEN * D_MODEL) {
        int l = i / D_MODEL, d = i - l * D_MODEL;
        g_x[i] = rna_tf32(emb[(size_t)tokens[l] * D_MODEL + d]);
    }
}

__global__ void padw_kernel(const float* __restrict__ xw, int L) {
    int i = blockIdx.x * 256 + threadIdx.x;
    if (i >= 256 * DI_) return;
    int row = i / DI_, col = i - row * DI_;
    g_wpad[i] = (row < 80) ? rna_tf32(xw[((size_t)L * 80 + row) * DI_ + col]) : 0.0f;
}

__global__ void paddt_kernel(const float* __restrict__ dw, int L) {
    int i = blockIdx.x * 256 + threadIdx.x;
    if (i >= DI_ * 64) return;
    int row = i >> 6, col = i & 63;
    g_dtwpad[i] = (col < DTRANK) ? rna_tf32(dw[((size_t)L * DI_ + row) * DTRANK + col]) : 0.0f;
}

__global__ void conv_silu_kernel(const float* __restrict__ conv_w,
                                 const float* __restrict__ conv_b, int layer) {
    int i = blockIdx.x * blockDim.x + threadIdx.x;
    if (i >= S_LEN * DI_) return;
    int t = i / DI_, c = i - t * DI_;
    const float* w = conv_w + ((size_t)layer * DI_ + c) * K_CONV;
    float acc = conv_b[layer * DI_ + c];
#pragma unroll
    for (int k = 0; k < K_CONV; k++) {
        int tt = t - (K_CONV - 1) + k;
        if (tt >= 0) acc += w[k] * g_xz[(size_t)tt * 2 * DI_ + c];
    }
    g_xs[i] = rna_tf32(silu_f(acc));
}

// ---------------- chunked selective scan ----------------
// phase 1: local scans per chunk; y_raw = sum_n C*h_local; per-(c,n) P, H
__global__ __launch_bounds__(256)
void scan_p1(const float* __restrict__ A_log, const float* __restrict__ dt_b, int layer) {
    int n  = threadIdx.x & 15;
    int cl = threadIdx.x >> 4;
    int c  = blockIdx.x * 16 + cl;
    int j  = blockIdx.y;
    float Acn  = -expf(A_log[((size_t)layer * DI_ + c) * N_ST + n]);
    float bias = dt_b[layer * DI_ + c];
    float h = 0.0f, p = 1.0f;
    int t0 = j * CLEN;
    for (int t = t0; t < t0 + CLEN; t++) {
        float a   = g_dtl[(size_t)t * DI_ + c] + bias;
        float dtv = (a > 20.0f) ? a : log1pf(__expf(a));
        float xv  = g_xs[(size_t)t * DI_ + c];
        float Bv  = g_xdbl[(size_t)t * XDP + DTRANK + n];
        float Cv  = g_xdbl[(size_t)t * XDP + DTRANK + N_ST + n];
        float dA  = __expf(dtv * Acn);
        h = dA * h + dtv * Bv * xv;
        p *= dA;
        float v = h * Cv;
#pragma unroll
        for (int o = 8; o > 0; o >>= 1)
            v += __shfl_down_sync(0xffffffffu, v, o, 16);
        if (n == 0) g_y[(size_t)t * DI_ + c] = v;
    }
    int idx = c * N_ST + n;
    g_P[j * GROUPS + idx] = p;
    g_H[j * GROUPS + idx] = h;
}

// phase 2: sequential carry combine across chunks
__global__ void scan_p2() {
    int idx = blockIdx.x * blockDim.x + threadIdx.x;
    if (idx >= GROUPS) return;
    float carry = 0.0f;
#pragma unroll
    for (int j = 0; j < NCHUNK; j++) {
        g_C0[j * GROUPS + idx] = carry;
        carry = g_H[j * GROUPS + idx] + g_P[j * GROUPS + idx] * carry;
    }
}

// phase 3: add carry corrections (chunks 1..7)
__global__ __launch_bounds__(256)
void scan_p3(const float* __restrict__ A_log, const float* __restrict__ dt_b, int layer) {
    int n  = threadIdx.x & 15;
    int cl = threadIdx.x >> 4;
    int c  = blockIdx.x * 16 + cl;
    int j  = blockIdx.y + 1;
    float Acn  = -expf(A_log[((size_t)layer * DI_ + c) * N_ST + n]);
    float bias = dt_b[layer * DI_ + c];
    float carry = g_C0[j * GROUPS + c * N_ST + n];
    float p = 1.0f;
    int t0 = j * CLEN;
    for (int t = t0; t < t0 + CLEN; t++) {
        float a   = g_dtl[(size_t)t * DI_ + c] + bias;
        float dtv = (a > 20.0f) ? a : log1pf(__expf(a));
        float Cv  = g_xdbl[(size_t)t * XDP + DTRANK + N_ST + n];
        p *= __expf(dtv * Acn);
        float v = Cv * p * carry;
#pragma unroll
        for (int o = 8; o > 0; o >>= 1)
            v += __shfl_down_sync(0xffffffffu, v, o, 16);
        if (n == 0) g_y[(size_t)t * DI_ + c] += v;
    }
}

// gate: y = (y + xs*Dp) * silu(z), rounded to tf32
__global__ void gate_kernel(const float* __restrict__ Dp, int layer) {
    int i = blockIdx.x * blockDim.x + threadIdx.x;
    if (i >= S_LEN * DI_) return;
    int t = i / DI_, c = i - t * DI_;
    float z = g_xz[(size_t)t * 2 * DI_ + DI_ + c];
    g_y[i] = rna_tf32((g_y[i] + g_xs[i] * Dp[layer * DI_ + c]) * silu_f(z));
}

__global__ __launch_bounds__(256)
void ln_kernel(const float* __restrict__ gam, const float* __restrict__ bet, int layer) {
    int l = blockIdx.x;
    __shared__ float rsum[8], rsq[8];
    float sum = 0.0f, sq = 0.0f;
    for (int d = threadIdx.x; d < D_MODEL; d += 256) {
        float v = g_x[(size_t)l * D_MODEL + d] + g_tmp[(size_t)l * D_MODEL + d];
        sum += v; sq += v * v;
    }
#pragma unroll
    for (int o = 16; o > 0; o >>= 1) {
        sum += __shfl_down_sync(0xffffffffu, sum, o);
        sq  += __shfl_down_sync(0xffffffffu, sq, o);
    }
    int wid = threadIdx.x >> 5;
    if ((threadIdx.x & 31) == 0) { rsum[wid] = sum; rsq[wid] = sq; }
    __syncthreads();
    if (threadIdx.x == 0) {
        float s = 0.0f, q = 0.0f;
#pragma unroll
        for (int w = 0; w < 8; w++) { s += rsum[w]; q += rsq[w]; }
        rsum[0] = s; rsq[0] = q;
    }
    __syncthreads();
    float mu  = rsum[0] / (float)D_MODEL;
    float var = rsq[0] / (float)D_MODEL - mu * mu;
    float rinv = rsqrtf(var + 1e-5f);
    for (int d = threadIdx.x; d < D_MODEL; d += 256) {
        float v = g_x[(size_t)l * D_MODEL + d] + g_tmp[(size_t)l * D_MODEL + d];
        g_x[(size_t)l * D_MODEL + d] = rna_tf32(
            (v - mu) * rinv * gam[layer * D_MODEL + d] + bet[layer * D_MODEL + d]);
    }
}

// ---------------- launch ----------------
extern "C" void kernel_launch(void* const* d_in, const int* in_sizes, int n_in,
                              void* d_out, int out_size) {
    const int*   tokens  = (const int*)  d_in[0];
    const float* emb     = (const float*)d_in[1];
    const float* in_w    = (const float*)d_in[2];
    const float* conv_w  = (const float*)d_in[3];
    const float* conv_b  = (const float*)d_in[4];
    const float* xproj_w = (const float*)d_in[5];
    const float* dt_w    = (const float*)d_in[6];
    const float* dt_b    = (const float*)d_in[7];
    const float* A_log   = (const float*)d_in[8];
    const float* Dp      = (const float*)d_in[9];
    const float* out_w   = (const float*)d_in[10];
    const float* ln_g    = (const float*)d_in[11];
    const float* ln_b    = (const float*)d_in[12];
    const float* head_w  = (const float*)d_in[13];
    float* out = (float*)d_out;

    static float *px = nullptr, *pxz, *pxs, *pxdbl, *pdtl, *py, *ptmp,
                 *pwpad, *pdtw, *pwbig, *pwout, *pwh;
    if (!px) {
        cudaGetSymbolAddress((void**)&pxz,   g_xz);
        cudaGetSymbolAddress((void**)&pxs,   g_xs);
        cudaGetSymbolAddress((void**)&pxdbl, g_xdbl);
        cudaGetSymbolAddress((void**)&pdtl,  g_dtl);
        cudaGetSymbolAddress((void**)&py,    g_y);
        cudaGetSymbolAddress((void**)&ptmp,  g_tmp);
        cudaGetSymbolAddress((void**)&pwpad, g_wpad);
        cudaGetSymbolAddress((void**)&pdtw,  g_dtwpad);
        cudaGetSymbolAddress((void**)&pwbig, g_wbig);
        cudaGetSymbolAddress((void**)&pwout, g_wout);
        cudaGetSymbolAddress((void**)&pwh,   g_wh);
        cudaFuncSetAttribute(gemm_mma<128, 256, 64, 64, false>,
                             cudaFuncAttributeMaxDynamicSharedMemorySize, SMEM_BIG);
        cudaFuncSetAttribute(gemm_mma<128, 128, 64, 32, false>,
                             cudaFuncAttributeMaxDynamicSharedMemorySize, SMEM_SMALL);
        cudaFuncSetAttribute(gemm_mma<128, 128, 64, 32, true>,
                             cudaFuncAttributeMaxDynamicSharedMemorySize, SMEM_SMALL);
        cudaGetSymbolAddress((void**)&px,    g_x);
    }

    embed_kernel<<<(S_LEN * D_MODEL + 255) / 256, 256>>>(tokens, emb);
    roundcopy4<<<(VOCAB * D_MODEL / 4 + 255) / 256, 256>>>(
        (float4*)pwh, (const float4*)head_w, VOCAB * D_MODEL / 4);

    for (int L = 0; L < NL_; L++) {
        roundcopy4<<<(2 * DI_ * D_MODEL / 4 + 255) / 256, 256>>>(
            (float4*)pwbig, (const float4*)(in_w + (size_t)L * 2 * DI_ * D_MODEL),
            2 * DI_ * D_MODEL / 4);
        padw_kernel<<<(256 * DI_ + 255) / 256, 256>>>(xproj_w, L);
        paddt_kernel<<<(DI_ * 64 + 255) / 256, 256>>>(dt_w, L);

        gemm_mma<128, 256, 64, 64, false><<<dim3(S_LEN / 128, 2 * DI_ / 256), 256, SMEM_BIG>>>(
            px, pwbig, pxz, D_MODEL, D_MODEL, D_MODEL, 2 * DI_);
        conv_silu_kernel<<<(S_LEN * DI_ + 255) / 256, 256>>>(conv_w, conv_b, L);

        gemm_mma<128, 128, 64, 32, true><<<dim3(S_LEN / 128, XDP / 128), 256, SMEM_SMALL>>>(
            pxs, pwpad, pxdbl, DI_, DI_, DI_, XDP);

        gemm_mma<128, 128, 64, 32, false><<<dim3(S_LEN / 128, DI_ / 128), 256, SMEM_SMALL>>>(
            pxdbl, pdtw, pdtl, 64, XDP, 64, DI_);

        scan_p1<<<dim3(DI_ / 16, NCHUNK), 256>>>(A_log, dt_b, L);
        scan_p2<<<(GROUPS + 255) / 256, 256>>>();
        scan_p3<<<dim3(DI_ / 16, NCHUNK - 1), 256>>>(A_log, dt_b, L);
        gate_kernel<<<(S_LEN * DI_ + 255) / 256, 256>>>(Dp, L);

        roundcopy4<<<(D_MODEL * DI_ / 4 + 255) / 256, 256>>>(
            (float4*)pwout, (const float4*)(out_w + (size_t)L * D_MODEL * DI_),
            D_MODEL * DI_ / 4);
        gemm_mma<128, 128, 64, 32, false><<<dim3(S_LEN / 128, D_MODEL / 128), 256, SMEM_SMALL>>>(
            py, pwout, ptmp, DI_, DI_, DI_, D_MODEL);

        ln_kernel<<<S_LEN, 256>>>(ln_g, ln_b, L);
    }

    gemm_mma<128, 256, 64, 64, false><<<dim3(S_LEN / 128, VOCAB / 256), 256, SMEM_BIG>>>(
        px, pwh, out, D_MODEL, D_MODEL, D_MODEL, VOCAB);
}

// round 5
// speedup vs baseline: 3.9952x; 1.1351x over previous
#include <cuda_runtime.h>
#include <cstdint>
#include <math.h>

#define S_LEN   1024
#define D_MODEL 768
#define DI_     1536
#define N_ST    16
#define K_CONV  4
#define DTRANK  48
#define XDP     256
#define VOCAB   32000
#define NL_     2
#define NCHUNK  8
#define CLEN    128
#define GROUPS  (DI_ * N_ST)

// ---------------- scratch ----------------
__device__ __align__(128) float g_x     [S_LEN * D_MODEL];
__device__ __align__(128) float g_xz    [S_LEN * 2 * DI_];
__device__ __align__(128) float g_xs    [S_LEN * DI_];
__device__ __align__(128) float g_xdbl  [S_LEN * XDP];
__device__ __align__(128) float g_dtl   [S_LEN * DI_];
__device__ __align__(128) float g_y     [S_LEN * DI_];
__device__ __align__(128) float g_tmp   [S_LEN * D_MODEL];
__device__ __align__(128) float g_wpad  [NL_][256 * DI_];
__device__ __align__(128) float g_dtwpad[NL_][DI_ * 64];
__device__ __align__(128) float g_wbig  [NL_][2 * DI_ * D_MODEL];
__device__ __align__(128) float g_wout  [NL_][D_MODEL * DI_];
__device__ __align__(128) float g_wh    [VOCAB * D_MODEL];
__device__ __align__(128) float g_P     [NCHUNK * GROUPS];
__device__ __align__(128) float g_H     [NCHUNK * GROUPS];
__device__ __align__(128) float g_C0    [NCHUNK * GROUPS];

// ---------------- helpers ----------------
__device__ __forceinline__ uint32_t smem_u32(const void* p) {
    uint32_t a;
    asm("{ .reg .u64 t; cvta.to.shared.u64 t, %1; cvt.u32.u64 %0, t; }" : "=r"(a) : "l"(p));
    return a;
}
__device__ __forceinline__ float rna_tf32(float v) {
    uint32_t t;
    asm("cvt.rna.tf32.f32 %0, %1;" : "=r"(t) : "f"(v));
    return __uint_as_float(t);
}
__device__ __forceinline__ float silu_f(float x) { return x / (1.0f + __expf(-x)); }

#define CP_ASYNC16(dst, src) \
    asm volatile("cp.async.cg.shared.global [%0], [%1], 16;" :: "r"(dst), "l"(src))
#define CP_COMMIT() asm volatile("cp.async.commit_group;" ::: "memory")
#define CP_WAIT(n)  asm volatile("cp.async.wait_group %0;" :: "n"(n) : "memory")
#define LDSM4(d0, d1, d2, d3, a) \
    asm volatile("ldmatrix.sync.aligned.m8n8.x4.shared.b16 {%0,%1,%2,%3}, [%4];" \
        : "=r"(d0), "=r"(d1), "=r"(d2), "=r"(d3) : "r"(a))

__device__ __forceinline__ void mma_tf32(float* c, const uint32_t* a, const uint32_t* b) {
    asm volatile(
        "mma.sync.aligned.m16n8k8.row.col.f32.tf32.tf32.f32 "
        "{%0,%1,%2,%3}, {%4,%5,%6,%7}, {%8,%9}, {%0,%1,%2,%3};"
        : "+f"(c[0]), "+f"(c[1]), "+f"(c[2]), "+f"(c[3])
        : "r"(a[0]), "r"(a[1]), "r"(a[2]), "r"(a[3]), "r"(b[0]), "r"(b[1]));
}

// ---------------- tf32 mma GEMM: C[M,N] = A[M,K] * B[N,K]^T (pre-rounded inputs) ----
template<int BM, int BN, int WM, int WN, bool RC>
__global__ __launch_bounds__((BM / WM) * (BN / WN) * 32)
void gemm_mma(const float* __restrict__ A, const float* __restrict__ B,
              float* __restrict__ C, int K, int lda, int ldb, int ldc)
{
    extern __shared__ float smem[];
    constexpr int T    = (BM / WM) * (BN / WN) * 32;
    constexpr int ASTG = BM * 32;
    constexpr int BSTG = BN * 32;
    constexpr int MF = WM / 16, NF = WN / 8, NP = NF / 2;
    constexpr int WCOLS = BN / WN;
    constexpr int AIT = (BM * 8) / T;
    constexpr int BIT = (BN * 8) / T;

    const int tid = threadIdx.x, lane = tid & 31, wid = tid >> 5;
    const int wm = wid / WCOLS, wn = wid % WCOLS;
    const int bm = blockIdx.x * BM, bn = blockIdx.y * BN;
    const int nc = K >> 5;
    const int lr = lane & 7, lg = lane >> 3;

    const uint32_t sb = smem_u32(smem);
    const float* Ab = A + (size_t)bm * lda;
    const float* Bb = B + (size_t)bn * ldb;

    auto loadA = [&](int chunk, int st) {
        uint32_t d0 = sb + st * (ASTG * 4);
        const float* s0 = Ab + chunk * 32;
#pragma unroll
        for (int it = 0; it < AIT; it++) {
            int i = tid + it * T;
            int r = i >> 3, q = i & 7;
            uint32_t off = ((uint32_t)r << 7) | (((uint32_t)q << 4) ^ (((uint32_t)(r & 7)) << 4));
            CP_ASYNC16(d0 + off, s0 + (size_t)r * lda + q * 4);
        }
    };
    auto loadB = [&](int chunk, int st) {
        uint32_t d0 = sb + (3 * ASTG + st * BSTG) * 4;
        const float* s0 = Bb + chunk * 32;
#pragma unroll
        for (int it = 0; it < BIT; it++) {
            int i = tid + it * T;
            int r = i >> 3, q = i & 7;
            uint32_t off = ((uint32_t)r << 7) | (((uint32_t)q << 4) ^ (((uint32_t)(r & 7)) << 4));
            CP_ASYNC16(d0 + off, s0 + (size_t)r * ldb + q * 4);
        }
    };

    const int a_row0 = wm * WM + ((lg & 1) << 3) + lr;
    const int a_coff = (lg >> 1) << 2;
    const int b_row0 = wn * WN + ((lg & 2) << 2) + lr;
    const int b_coff = (lg & 1) << 2;
    const uint32_t sw = (uint32_t)lr << 4;

    float acc[MF][NF][4];
#pragma unroll
    for (int i = 0; i < MF; i++)
#pragma unroll
        for (int j = 0; j < NF; j++)
#pragma unroll
            for (int v = 0; v < 4; v++) acc[i][j][v] = 0.0f;

    int npre = nc < 2 ? nc : 2;
    for (int c = 0; c < npre; c++) { loadA(c, c); loadB(c, c); CP_COMMIT(); }

    for (int i = 0; i < nc; i++) {
        if (i + 2 < nc) { CP_WAIT(1); } else { CP_WAIT(0); }
        __syncthreads();
        if (i + 2 < nc) {
            int s2 = (i + 2) % 3;
            loadA(i + 2, s2); loadB(i + 2, s2); CP_COMMIT();
        }
        uint32_t abase = sb + (i % 3) * (ASTG * 4);
        uint32_t bbase = sb + (3 * ASTG + (i % 3) * BSTG) * 4;
#pragma unroll
        for (int ks = 0; ks < 4; ks++) {
            const int k0 = ks * 8;
            uint32_t afr[MF][4];
#pragma unroll
            for (int mf = 0; mf < MF; mf++) {
                uint32_t ad = abase + (uint32_t)(a_row0 + mf * 16) * 128 +
                              ((((uint32_t)(k0 + a_coff)) << 2) ^ sw);
                LDSM4(afr[mf][0], afr[mf][1], afr[mf][2], afr[mf][3], ad);
            }
            uint32_t bfr[NF][2];
#pragma unroll
            for (int p = 0; p < NP; p++) {
                uint32_t bd = bbase + (uint32_t)(b_row0 + p * 16) * 128 +
                              ((((uint32_t)(k0 + b_coff)) << 2) ^ sw);
                LDSM4(bfr[2 * p][0], bfr[2 * p][1], bfr[2 * p + 1][0], bfr[2 * p + 1][1], bd);
            }
#pragma unroll
            for (int mf = 0; mf < MF; mf++)
#pragma unroll
                for (int nf = 0; nf < NF; nf++)
                    mma_tf32(acc[mf][nf], afr[mf], bfr[nf]);
        }
    }

#pragma unroll
    for (int mf = 0; mf < MF; mf++) {
        int row = bm + wm * WM + mf * 16 + (lane >> 2);
#pragma unroll
        for (int nf = 0; nf < NF; nf++) {
            int col = bn + wn * WN + nf * 8 + 2 * (lane & 3);
            float v0 = acc[mf][nf][0], v1 = acc[mf][nf][1];
            float v2 = acc[mf][nf][2], v3 = acc[mf][nf][3];
            if (RC) { v0 = rna_tf32(v0); v1 = rna_tf32(v1); v2 = rna_tf32(v2); v3 = rna_tf32(v3); }
            *(float2*)(C + (size_t)row * ldc + col)       = make_float2(v0, v1);
            *(float2*)(C + (size_t)(row + 8) * ldc + col) = make_float2(v2, v3);
        }
    }
}

#define SMEM_BIG   (3 * (128 * 32 + 128 * 32) * 4)
#define SMEM_SMALL (3 * (64 * 32 + 64 * 32) * 4)

// ---------------- elementwise / small kernels ----------------
__global__ void roundcopy4(float4* __restrict__ dst, const float4* __restrict__ src, int n4) {
    int i = blockIdx.x * blockDim.x + threadIdx.x;
    if (i < n4) {
        float4 v = src[i];
        v.x = rna_tf32(v.x); v.y = rna_tf32(v.y);
        v.z = rna_tf32(v.z); v.w = rna_tf32(v.w);
        dst[i] = v;
    }
}

__global__ void embed_kernel(const int* __restrict__ tokens,
                             const float* __restrict__ emb) {
    int i = blockIdx.x * blockDim.x + threadIdx.x;
    if (i < S_LEN * D_MODEL) {
        int l = i / D_MODEL, d = i - l * D_MODEL;
        g_x[i] = rna_tf32(emb[(size_t)tokens[l] * D_MODEL + d]);
    }
}

__global__ void padw_kernel(const float* __restrict__ xw, int L) {
    int i = blockIdx.x * 256 + threadIdx.x;
    if (i >= 256 * DI_) return;
    int row = i / DI_, col = i - row * DI_;
    g_wpad[L][i] = (row < 80) ? rna_tf32(xw[((size_t)L * 80 + row) * DI_ + col]) : 0.0f;
}

__global__ void paddt_kernel(const float* __restrict__ dw, int L) {
    int i = blockIdx.x * 256 + threadIdx.x;
    if (i >= DI_ * 64) return;
    int row = i >> 6, col = i & 63;
    g_dtwpad[L][i] = (col < DTRANK) ? rna_tf32(dw[((size_t)L * DI_ + row) * DTRANK + col]) : 0.0f;
}

__global__ void conv_silu_kernel(const float* __restrict__ conv_w,
                                 const float* __restrict__ conv_b, int layer) {
    int i = blockIdx.x * blockDim.x + threadIdx.x;
    if (i >= S_LEN * DI_) return;
    int t = i / DI_, c = i - t * DI_;
    const float* w = conv_w + ((size_t)layer * DI_ + c) * K_CONV;
    float acc = conv_b[layer * DI_ + c];
#pragma unroll
    for (int k = 0; k < K_CONV; k++) {
        int tt = t - (K_CONV - 1) + k;
        if (tt >= 0) acc += w[k] * g_xz[(size_t)tt * 2 * DI_ + c];
    }
    g_xs[i] = rna_tf32(silu_f(acc));
}

// ---------------- chunked selective scan ----------------
// p1: local scans; writes softplus(dt) back into g_dtl in-place
__global__ __launch_bounds__(256)
void scan_p1(const float* __restrict__ A_log, const float* __restrict__ dt_b, int layer) {
    int n  = threadIdx.x & 15;
    int cl = threadIdx.x >> 4;
    int c  = blockIdx.x * 16 + cl;
    int j  = blockIdx.y;
    float Acn  = -expf(A_log[((size_t)layer * DI_ + c) * N_ST + n]);
    float bias = dt_b[layer * DI_ + c];
    float h = 0.0f, p = 1.0f;
    int t0 = j * CLEN;
    for (int t = t0; t < t0 + CLEN; t++) {
        float a   = g_dtl[(size_t)t * DI_ + c] + bias;
        float dtv = (a > 20.0f) ? a : log1pf(__expf(a));
        float xv  = g_xs[(size_t)t * DI_ + c];
        float Bv  = g_xdbl[(size_t)t * XDP + DTRANK + n];
        float Cv  = g_xdbl[(size_t)t * XDP + DTRANK + N_ST + n];
        float dA  = __expf(dtv * Acn);
        h = dA * h + dtv * Bv * xv;
        p *= dA;
        float v = h * Cv;
#pragma unroll
        for (int o = 8; o > 0; o >>= 1)
            v += __shfl_down_sync(0xffffffffu, v, o, 16);
        if (n == 0) {
            g_y[(size_t)t * DI_ + c] = v;
            g_dtl[(size_t)t * DI_ + c] = dtv;     // cache softplus for p3
        }
    }
    int idx = c * N_ST + n;
    g_P[j * GROUPS + idx] = p;
    g_H[j * GROUPS + idx] = h;
}

__global__ void scan_p2() {
    int idx = blockIdx.x * blockDim.x + threadIdx.x;
    if (idx >= GROUPS) return;
    float carry = 0.0f;
#pragma unroll
    for (int j = 0; j < NCHUNK; j++) {
        g_C0[j * GROUPS + idx] = carry;
        carry = g_H[j * GROUPS + idx] + g_P[j * GROUPS + idx] * carry;
    }
}

// p3: carry correction + fused gate (all chunks)
__global__ __launch_bounds__(256)
void scan_p3(const float* __restrict__ A_log, const float* __restrict__ Dp, int layer) {
    int n  = threadIdx.x & 15;
    int cl = threadIdx.x >> 4;
    int c  = blockIdx.x * 16 + cl;
    int j  = blockIdx.y;
    float Acn = -expf(A_log[((size_t)layer * DI_ + c) * N_ST + n]);
    float Dpc = Dp[layer * DI_ + c];
    float carry = g_C0[j * GROUPS + c * N_ST + n];
    float p = 1.0f;
    int t0 = j * CLEN;
    if (j > 0) {
        for (int t = t0; t < t0 + CLEN; t++) {
            float dtv = g_dtl[(size_t)t * DI_ + c];
            float Cv  = g_xdbl[(size_t)t * XDP + DTRANK + N_ST + n];
            p *= __expf(dtv * Acn);
            float v = Cv * p * carry;
#pragma unroll
            for (int o = 8; o > 0; o >>= 1)
                v += __shfl_down_sync(0xffffffffu, v, o, 16);
            if (n == 0) {
                float xv = g_xs[(size_t)t * DI_ + c];
                float z  = g_xz[(size_t)t * 2 * DI_ + DI_ + c];
                g_y[(size_t)t * DI_ + c] =
                    rna_tf32((g_y[(size_t)t * DI_ + c] + v + xv * Dpc) * silu_f(z));
            }
        }
    } else {
        if (n == 0) {
            for (int t = t0; t < t0 + CLEN; t++) {
                float xv = g_xs[(size_t)t * DI_ + c];
                float z  = g_xz[(size_t)t * 2 * DI_ + DI_ + c];
                g_y[(size_t)t * DI_ + c] =
                    rna_tf32((g_y[(size_t)t * DI_ + c] + xv * Dpc) * silu_f(z));
            }
        }
    }
}

__global__ __launch_bounds__(256)
void ln_kernel(const float* __restrict__ gam, const float* __restrict__ bet, int layer) {
    int l = blockIdx.x;
    __shared__ float rsum[8], rsq[8];
    float sum = 0.0f, sq = 0.0f;
    for (int d = threadIdx.x; d < D_MODEL; d += 256) {
        float v = g_x[(size_t)l * D_MODEL + d] + g_tmp[(size_t)l * D_MODEL + d];
        sum += v; sq += v * v;
    }
#pragma unroll
    for (int o = 16; o > 0; o >>= 1) {
        sum += __shfl_down_sync(0xffffffffu, sum, o);
        sq  += __shfl_down_sync(0xffffffffu, sq, o);
    }
    int wid = threadIdx.x >> 5;
    if ((threadIdx.x & 31) == 0) { rsum[wid] = sum; rsq[wid] = sq; }
    __syncthreads();
    if (threadIdx.x == 0) {
        float s = 0.0f, q = 0.0f;
#pragma unroll
        for (int w = 0; w < 8; w++) { s += rsum[w]; q += rsq[w]; }
        rsum[0] = s; rsq[0] = q;
    }
    __syncthreads();
    float mu  = rsum[0] / (float)D_MODEL;
    float var = rsq[0] / (float)D_MODEL - mu * mu;
    float rinv = rsqrtf(var + 1e-5f);
    for (int d = threadIdx.x; d < D_MODEL; d += 256) {
        float v = g_x[(size_t)l * D_MODEL + d] + g_tmp[(size_t)l * D_MODEL + d];
        g_x[(size_t)l * D_MODEL + d] = rna_tf32(
            (v - mu) * rinv * gam[layer * D_MODEL + d] + bet[layer * D_MODEL + d]);
    }
}

// ---------------- launch ----------------
extern "C" void kernel_launch(void* const* d_in, const int* in_sizes, int n_in,
                              void* d_out, int out_size) {
    const int*   tokens  = (const int*)  d_in[0];
    const float* emb     = (const float*)d_in[1];
    const float* in_w    = (const float*)d_in[2];
    const float* conv_w  = (const float*)d_in[3];
    const float* conv_b  = (const float*)d_in[4];
    const float* xproj_w = (const float*)d_in[5];
    const float* dt_w    = (const float*)d_in[6];
    const float* dt_b    = (const float*)d_in[7];
    const float* A_log   = (const float*)d_in[8];
    const float* Dp      = (const float*)d_in[9];
    const float* out_w   = (const float*)d_in[10];
    const float* ln_g    = (const float*)d_in[11];
    const float* ln_b    = (const float*)d_in[12];
    const float* head_w  = (const float*)d_in[13];
    float* out = (float*)d_out;

    static float *px = nullptr, *pxz, *pxs, *pxdbl, *pdtl, *py, *ptmp, *pwh;
    static float *pwpad[NL_], *pdtw[NL_], *pwbig[NL_], *pwout[NL_];
    static cudaStream_t s1;
    static cudaEvent_t evFork, evWh, evJoin;
    static cudaEvent_t evIn[NL_], evPP[NL_], evOw[NL_];
    if (!px) {
        cudaGetSymbolAddress((void**)&pxz,   g_xz);
        cudaGetSymbolAddress((void**)&pxs,   g_xs);
        cudaGetSymbolAddress((void**)&pxdbl, g_xdbl);
        cudaGetSymbolAddress((void**)&pdtl,  g_dtl);
        cudaGetSymbolAddress((void**)&py,    g_y);
        cudaGetSymbolAddress((void**)&ptmp,  g_tmp);
        cudaGetSymbolAddress((void**)&pwh,   g_wh);
        float* base;
        cudaGetSymbolAddress((void**)&base, g_wpad);
        for (int L = 0; L < NL_; L++) pwpad[L] = base + (size_t)L * 256 * DI_;
        cudaGetSymbolAddress((void**)&base, g_dtwpad);
        for (int L = 0; L < NL_; L++) pdtw[L] = base + (size_t)L * DI_ * 64;
        cudaGetSymbolAddress((void**)&base, g_wbig);
        for (int L = 0; L < NL_; L++) pwbig[L] = base + (size_t)L * 2 * DI_ * D_MODEL;
        cudaGetSymbolAddress((void**)&base, g_wout);
        for (int L = 0; L < NL_; L++) pwout[L] = base + (size_t)L * D_MODEL * DI_;
        cudaFuncSetAttribute(gemm_mma<128, 128, 64, 32, false>,
                             cudaFuncAttributeMaxDynamicSharedMemorySize, SMEM_BIG);
        cudaFuncSetAttribute(gemm_mma<64, 64, 32, 32, false>,
                             cudaFuncAttributeMaxDynamicSharedMemorySize, SMEM_SMALL);
        cudaFuncSetAttribute(gemm_mma<64, 64, 32, 32, true>,
                             cudaFuncAttributeMaxDynamicSharedMemorySize, SMEM_SMALL);
        cudaStreamCreateWithFlags(&s1, cudaStreamNonBlocking);
        cudaEventCreateWithFlags(&evFork, cudaEventDisableTiming);
        cudaEventCreateWithFlags(&evWh,   cudaEventDisableTiming);
        cudaEventCreateWithFlags(&evJoin, cudaEventDisableTiming);
        for (int L = 0; L < NL_; L++) {
            cudaEventCreateWithFlags(&evIn[L], cudaEventDisableTiming);
            cudaEventCreateWithFlags(&evPP[L], cudaEventDisableTiming);
            cudaEventCreateWithFlags(&evOw[L], cudaEventDisableTiming);
        }
        cudaGetSymbolAddress((void**)&px, g_x);
    }

    // fork side stream for weight preprocessing
    cudaEventRecord(evFork, 0);
    cudaStreamWaitEvent(s1, evFork, 0);

    embed_kernel<<<(S_LEN * D_MODEL + 255) / 256, 256>>>(tokens, emb);          // idx 0

    roundcopy4<<<(2 * DI_ * D_MODEL / 4 + 255) / 256, 256, 0, s1>>>(            // idx 1
        (float4*)pwbig[0], (const float4*)in_w, 2 * DI_ * D_MODEL / 4);
    cudaEventRecord(evIn[0], s1);
    padw_kernel<<<(256 * DI_ + 255) / 256, 256, 0, s1>>>(xproj_w, 0);           // idx 2

    // in-proj L0 at launch index 3 (profiled)
    cudaStreamWaitEvent(0, evIn[0], 0);
    gemm_mma<128, 128, 64, 32, false><<<dim3(S_LEN / 128, 2 * DI_ / 128), 256, SMEM_BIG>>>(
        px, pwbig[0], pxz, D_MODEL, D_MODEL, D_MODEL, 2 * DI_);                 // idx 3

    // remaining side-stream preprocessing
    paddt_kernel<<<(DI_ * 64 + 255) / 256, 256, 0, s1>>>(dt_w, 0);
    cudaEventRecord(evPP[0], s1);
    roundcopy4<<<(D_MODEL * DI_ / 4 + 255) / 256, 256, 0, s1>>>(
        (float4*)pwout[0], (const float4*)out_w, D_MODEL * DI_ / 4);
    cudaEventRecord(evOw[0], s1);
    roundcopy4<<<(2 * DI_ * D_MODEL / 4 + 255) / 256, 256, 0, s1>>>(
        (float4*)pwbig[1], (const float4*)(in_w + (size_t)2 * DI_ * D_MODEL),
        2 * DI_ * D_MODEL / 4);
    cudaEventRecord(evIn[1], s1);
    padw_kernel<<<(256 * DI_ + 255) / 256, 256, 0, s1>>>(xproj_w, 1);
    paddt_kernel<<<(DI_ * 64 + 255) / 256, 256, 0, s1>>>(dt_w, 1);
    cudaEventRecord(evPP[1], s1);
    roundcopy4<<<(D_MODEL * DI_ / 4 + 255) / 256, 256, 0, s1>>>(
        (float4*)pwout[1], (const float4*)(out_w + (size_t)D_MODEL * DI_),
        D_MODEL * DI_ / 4);
    cudaEventRecord(evOw[1], s1);
    roundcopy4<<<(VOCAB * D_MODEL / 4 + 255) / 256, 256, 0, s1>>>(
        (float4*)pwh, (const float4*)head_w, VOCAB * D_MODEL / 4);
    cudaEventRecord(evWh, s1);
    cudaEventRecord(evJoin, s1);

    for (int L = 0; L < NL_; L++) {
        if (L > 0) {
            cudaStreamWaitEvent(0, evIn[L], 0);
            gemm_mma<128, 128, 64, 32, false><<<dim3(S_LEN / 128, 2 * DI_ / 128), 256, SMEM_BIG>>>(
                px, pwbig[L], pxz, D_MODEL, D_MODEL, D_MODEL, 2 * DI_);
        }
        conv_silu_kernel<<<(S_LEN * DI_ + 255) / 256, 256>>>(conv_w, conv_b, L);

        cudaStreamWaitEvent(0, evPP[L], 0);
        gemm_mma<64, 64, 32, 32, true><<<dim3(S_LEN / 64, XDP / 64), 128, SMEM_SMALL>>>(
            pxs, pwpad[L], pxdbl, DI_, DI_, DI_, XDP);
        gemm_mma<64, 64, 32, 32, false><<<dim3(S_LEN / 64, DI_ / 64), 128, SMEM_SMALL>>>(
            pxdbl, pdtw[L], pdtl, 64, XDP, 64, DI_);

        scan_p1<<<dim3(DI_ / 16, NCHUNK), 256>>>(A_log, dt_b, L);
        scan_p2<<<(GROUPS + 255) / 256, 256>>>();
        scan_p3<<<dim3(DI_ / 16, NCHUNK), 256>>>(A_log, Dp, L);

        cudaStreamWaitEvent(0, evOw[L], 0);
        gemm_mma<64, 64, 32, 32, false><<<dim3(S_LEN / 64, D_MODEL / 64), 128, SMEM_SMALL>>>(
            py, pwout[L], ptmp, DI_, DI_, DI_, D_MODEL);

        ln_kernel<<<S_LEN, 256>>>(ln_g, ln_b, L);
    }

    cudaStreamWaitEvent(0, evWh, 0);
    cudaStreamWaitEvent(0, evJoin, 0);
    gemm_mma<128, 128, 64, 32, false><<<dim3(S_LEN / 128, VOCAB / 128), 256, SMEM_BIG>>>(
        px, pwh, out, D_MODEL, D_MODEL, D_MODEL, VOCAB);
}

// round 6
// speedup vs baseline: 4.0141x; 1.0047x over previous
#include <cuda_runtime.h>
#include <cstdint>
#include <math.h>

#define S_LEN   1024
#define D_MODEL 768
#define DI_     1536
#define N_ST    16
#define K_CONV  4
#define DTRANK  48
#define XDP     256
#define VOCAB   32000
#define NL_     2
#define NCHUNK  8
#define CLEN    128
#define GROUPS  (DI_ * N_ST)

// ---------------- scratch ----------------
__device__ __align__(128) float g_x     [S_LEN * D_MODEL];
__device__ __align__(128) float g_xz    [S_LEN * 2 * DI_];
__device__ __align__(128) float g_xs    [S_LEN * DI_];
__device__ __align__(128) float g_xdbl  [S_LEN * XDP];
__device__ __align__(128) float g_dtl   [S_LEN * DI_];
__device__ __align__(128) float g_y     [S_LEN * DI_];
__device__ __align__(128) float g_tmp   [S_LEN * D_MODEL];
__device__ __align__(128) float g_wpad  [NL_][256 * DI_];
__device__ __align__(128) float g_dtwpad[NL_][DI_ * 64];
__device__ __align__(128) float g_wbig  [NL_][2 * DI_ * D_MODEL];
__device__ __align__(128) float g_wout  [NL_][D_MODEL * DI_];
__device__ __align__(128) float g_wh    [VOCAB * D_MODEL];
__device__ __align__(128) float g_P     [NCHUNK * GROUPS];
__device__ __align__(128) float g_H     [NCHUNK * GROUPS];
__device__ __align__(128) float g_C0    [NCHUNK * GROUPS];

// ---------------- helpers ----------------
__device__ __forceinline__ uint32_t smem_u32(const void* p) {
    uint32_t a;
    asm("{ .reg .u64 t; cvta.to.shared.u64 t, %1; cvt.u32.u64 %0, t; }" : "=r"(a) : "l"(p));
    return a;
}
__device__ __forceinline__ float rna_tf32(float v) {
    uint32_t t;
    asm("cvt.rna.tf32.f32 %0, %1;" : "=r"(t) : "f"(v));
    return __uint_as_float(t);
}
__device__ __forceinline__ float silu_f(float x) { return x / (1.0f + __expf(-x)); }

#define CP_ASYNC16(dst, src) \
    asm volatile("cp.async.cg.shared.global [%0], [%1], 16;" :: "r"(dst), "l"(src))
#define CP_COMMIT() asm volatile("cp.async.commit_group;" ::: "memory")
#define CP_WAIT(n)  asm volatile("cp.async.wait_group %0;" :: "n"(n) : "memory")
#define LDSM4(d0, d1, d2, d3, a) \
    asm volatile("ldmatrix.sync.aligned.m8n8.x4.shared.b16 {%0,%1,%2,%3}, [%4];" \
        : "=r"(d0), "=r"(d1), "=r"(d2), "=r"(d3) : "r"(a))

__device__ __forceinline__ void mma_tf32(float* c, const uint32_t* a, const uint32_t* b) {
    asm volatile(
        "mma.sync.aligned.m16n8k8.row.col.f32.tf32.tf32.f32 "
        "{%0,%1,%2,%3}, {%4,%5,%6,%7}, {%8,%9}, {%0,%1,%2,%3};"
        : "+f"(c[0]), "+f"(c[1]), "+f"(c[2]), "+f"(c[3])
        : "r"(a[0]), "r"(a[1]), "r"(a[2]), "r"(a[3]), "r"(b[0]), "r"(b[1]));
}

// ---------------- big-tile GEMM: 128x128, 4 warps, WM=64 WN=64 -----------------
// C[M,N] = A[M,K] * B[N,K]^T, inputs pre-rounded tf32. grid=(M/128, N/128), block=128.
#define SMEM_BIG (3 * (128 * 32 + 128 * 32) * 4)
__global__ __launch_bounds__(128)
void gemm_big(const float* __restrict__ A, const float* __restrict__ B,
              float* __restrict__ C, int K, int lda, int ldb, int ldc)
{
    extern __shared__ float smem[];
    constexpr int ASTG = 128 * 32;
    constexpr int BSTG = 128 * 32;

    const int tid = threadIdx.x, lane = tid & 31, wid = tid >> 5;
    const int wm = wid >> 1, wn = wid & 1;         // 2x2 warp grid
    const int bm = blockIdx.x * 128, bn = blockIdx.y * 128;
    const int nc = K >> 5;
    const int lr = lane & 7, lg = lane >> 3;

    const uint32_t sb = smem_u32(smem);
    const float* Ab = A + (size_t)bm * lda;
    const float* Bb = B + (size_t)bn * ldb;

    auto loadA = [&](int chunk, int st) {
        uint32_t d0 = sb + st * (ASTG * 4);
        const float* s0 = Ab + chunk * 32;
#pragma unroll
        for (int it = 0; it < 8; it++) {
            int i = tid + it * 128;
            int r = i >> 3, q = i & 7;
            uint32_t off = ((uint32_t)r << 7) | (((uint32_t)q << 4) ^ (((uint32_t)(r & 7)) << 4));
            CP_ASYNC16(d0 + off, s0 + (size_t)r * lda + q * 4);
        }
    };
    auto loadB = [&](int chunk, int st) {
        uint32_t d0 = sb + (3 * ASTG + st * BSTG) * 4;
        const float* s0 = Bb + chunk * 32;
#pragma unroll
        for (int it = 0; it < 8; it++) {
            int i = tid + it * 128;
            int r = i >> 3, q = i & 7;
            uint32_t off = ((uint32_t)r << 7) | (((uint32_t)q << 4) ^ (((uint32_t)(r & 7)) << 4));
            CP_ASYNC16(d0 + off, s0 + (size_t)r * ldb + q * 4);
        }
    };

    const int a_row0 = wm * 64 + ((lg & 1) << 3) + lr;
    const int a_coff = (lg >> 1) << 2;
    const int b_row0 = wn * 64 + ((lg & 2) << 2) + lr;
    const int b_coff = (lg & 1) << 2;
    const uint32_t sw = (uint32_t)lr << 4;

    float acc[4][8][4];
#pragma unroll
    for (int i = 0; i < 4; i++)
#pragma unroll
        for (int j = 0; j < 8; j++)
#pragma unroll
            for (int v = 0; v < 4; v++) acc[i][j][v] = 0.0f;

    int npre = nc < 2 ? nc : 2;
    for (int c = 0; c < npre; c++) { loadA(c, c); loadB(c, c); CP_COMMIT(); }

    for (int i = 0; i < nc; i++) {
        if (i + 2 < nc) { CP_WAIT(1); } else { CP_WAIT(0); }
        __syncthreads();
        if (i + 2 < nc) {
            int s2 = (i + 2) % 3;
            loadA(i + 2, s2); loadB(i + 2, s2); CP_COMMIT();
        }
        uint32_t abase = sb + (i % 3) * (ASTG * 4);
        uint32_t bbase = sb + (3 * ASTG + (i % 3) * BSTG) * 4;
#pragma unroll
        for (int ks = 0; ks < 4; ks++) {
            const int k0 = ks * 8;
            uint32_t afr[4][4];
#pragma unroll
            for (int mf = 0; mf < 4; mf++) {
                uint32_t ad = abase + (uint32_t)(a_row0 + mf * 16) * 128 +
                              ((((uint32_t)(k0 + a_coff)) << 2) ^ sw);
                LDSM4(afr[mf][0], afr[mf][1], afr[mf][2], afr[mf][3], ad);
            }
            // stream B in two halves of 4 NF each (keeps bfr at 8 regs)
#pragma unroll
            for (int h = 0; h < 2; h++) {
                uint32_t bfr[4][2];
#pragma unroll
                for (int p = 0; p < 2; p++) {
                    uint32_t bd = bbase + (uint32_t)(b_row0 + (h * 2 + p) * 16) * 128 +
                                  ((((uint32_t)(k0 + b_coff)) << 2) ^ sw);
                    LDSM4(bfr[2 * p][0], bfr[2 * p][1], bfr[2 * p + 1][0], bfr[2 * p + 1][1], bd);
                }
#pragma unroll
                for (int mf = 0; mf < 4; mf++)
#pragma unroll
                    for (int nf = 0; nf < 4; nf++)
                        mma_tf32(acc[mf][h * 4 + nf], afr[mf], bfr[nf]);
            }
        }
    }

#pragma unroll
    for (int mf = 0; mf < 4; mf++) {
        int row = bm + wm * 64 + mf * 16 + (lane >> 2);
#pragma unroll
        for (int nf = 0; nf < 8; nf++) {
            int col = bn + wn * 64 + nf * 8 + 2 * (lane & 3);
            *(float2*)(C + (size_t)row * ldc + col) =
                make_float2(acc[mf][nf][0], acc[mf][nf][1]);
            *(float2*)(C + (size_t)(row + 8) * ldc + col) =
                make_float2(acc[mf][nf][2], acc[mf][nf][3]);
        }
    }
}

// ---------------- small GEMM: 64x64, 4 warps, WM=32 WN=32 ----------------------
#define SMEM_SMALL (3 * (64 * 32 + 64 * 32) * 4)
template<bool RC>
__global__ __launch_bounds__(128)
void gemm_small(const float* __restrict__ A, const float* __restrict__ B,
                float* __restrict__ C, int K, int lda, int ldb, int ldc)
{
    extern __shared__ float smem[];
    constexpr int ASTG = 64 * 32;
    constexpr int BSTG = 64 * 32;

    const int tid = threadIdx.x, lane = tid & 31, wid = tid >> 5;
    const int wm = wid >> 1, wn = wid & 1;
    const int bm = blockIdx.x * 64, bn = blockIdx.y * 64;
    const int nc = K >> 5;
    const int lr = lane & 7, lg = lane >> 3;

    const uint32_t sb = smem_u32(smem);
    const float* Ab = A + (size_t)bm * lda;
    const float* Bb = B + (size_t)bn * ldb;

    auto loadA = [&](int chunk, int st) {
        uint32_t d0 = sb + st * (ASTG * 4);
        const float* s0 = Ab + chunk * 32;
#pragma unroll
        for (int it = 0; it < 4; it++) {
            int i = tid + it * 128;
            int r = i >> 3, q = i & 7;
            uint32_t off = ((uint32_t)r << 7) | (((uint32_t)q << 4) ^ (((uint32_t)(r & 7)) << 4));
            CP_ASYNC16(d0 + off, s0 + (size_t)r * lda + q * 4);
        }
    };
    auto loadB = [&](int chunk, int st) {
        uint32_t d0 = sb + (3 * ASTG + st * BSTG) * 4;
        const float* s0 = Bb + chunk * 32;
#pragma unroll
        for (int it = 0; it < 4; it++) {
            int i = tid + it * 128;
            int r = i >> 3, q = i & 7;
            uint32_t off = ((uint32_t)r << 7) | (((uint32_t)q << 4) ^ (((uint32_t)(r & 7)) << 4));
            CP_ASYNC16(d0 + off, s0 + (size_t)r * ldb + q * 4);
        }
    };

    const int a_row0 = wm * 32 + ((lg & 1) << 3) + lr;
    const int a_coff = (lg >> 1) << 2;
    const int b_row0 = wn * 32 + ((lg & 2) << 2) + lr;
    const int b_coff = (lg & 1) << 2;
    const uint32_t sw = (uint32_t)lr << 4;

    float acc[2][4][4];
#pragma unroll
    for (int i = 0; i < 2; i++)
#pragma unroll
        for (int j = 0; j < 4; j++)
#pragma unroll
            for (int v = 0; v < 4; v++) acc[i][j][v] = 0.0f;

    int npre = nc < 2 ? nc : 2;
    for (int c = 0; c < npre; c++) { loadA(c, c); loadB(c, c); CP_COMMIT(); }

    for (int i = 0; i < nc; i++) {
        if (i + 2 < nc) { CP_WAIT(1); } else { CP_WAIT(0); }
        __syncthreads();
        if (i + 2 < nc) {
            int s2 = (i + 2) % 3;
            loadA(i + 2, s2); loadB(i + 2, s2); CP_COMMIT();
        }
        uint32_t abase = sb + (i % 3) * (ASTG * 4);
        uint32_t bbase = sb + (3 * ASTG + (i % 3) * BSTG) * 4;
#pragma unroll
        for (int ks = 0; ks < 4; ks++) {
            const int k0 = ks * 8;
            uint32_t afr[2][4];
#pragma unroll
            for (int mf = 0; mf < 2; mf++) {
                uint32_t ad = abase + (uint32_t)(a_row0 + mf * 16) * 128 +
                              ((((uint32_t)(k0 + a_coff)) << 2) ^ sw);
                LDSM4(afr[mf][0], afr[mf][1], afr[mf][2], afr[mf][3], ad);
            }
            uint32_t bfr[4][2];
#pragma unroll
            for (int p = 0; p < 2; p++) {
                uint32_t bd = bbase + (uint32_t)(b_row0 + p * 16) * 128 +
                              ((((uint32_t)(k0 + b_coff)) << 2) ^ sw);
                LDSM4(bfr[2 * p][0], bfr[2 * p][1], bfr[2 * p + 1][0], bfr[2 * p + 1][1], bd);
            }
#pragma unroll
            for (int mf = 0; mf < 2; mf++)
#pragma unroll
                for (int nf = 0; nf < 4; nf++)
                    mma_tf32(acc[mf][nf], afr[mf], bfr[nf]);
        }
    }

#pragma unroll
    for (int mf = 0; mf < 2; mf++) {
        int row = bm + wm * 32 + mf * 16 + (lane >> 2);
#pragma unroll
        for (int nf = 0; nf < 4; nf++) {
            int col = bn + wn * 32 + nf * 8 + 2 * (lane & 3);
            float v0 = acc[mf][nf][0], v1 = acc[mf][nf][1];
            float v2 = acc[mf][nf][2], v3 = acc[mf][nf][3];
            if (RC) { v0 = rna_tf32(v0); v1 = rna_tf32(v1); v2 = rna_tf32(v2); v3 = rna_tf32(v3); }
            *(float2*)(C + (size_t)row * ldc + col)       = make_float2(v0, v1);
            *(float2*)(C + (size_t)(row + 8) * ldc + col) = make_float2(v2, v3);
        }
    }
}

// ---------------- elementwise / small kernels ----------------
__global__ void roundcopy4(float4* __restrict__ dst, const float4* __restrict__ src, int n4) {
    int i = blockIdx.x * blockDim.x + threadIdx.x;
    if (i < n4) {
        float4 v = src[i];
        v.x = rna_tf32(v.x); v.y = rna_tf32(v.y);
        v.z = rna_tf32(v.z); v.w = rna_tf32(v.w);
        dst[i] = v;
    }
}

__global__ void embed_kernel(const int* __restrict__ tokens,
                             const float* __restrict__ emb) {
    int i = blockIdx.x * blockDim.x + threadIdx.x;
    if (i < S_LEN * D_MODEL) {
        int l = i / D_MODEL, d = i - l * D_MODEL;
        g_x[i] = rna_tf32(emb[(size_t)tokens[l] * D_MODEL + d]);
    }
}

__global__ void padw_kernel(const float* __restrict__ xw, int L) {
    int i = blockIdx.x * 256 + threadIdx.x;
    if (i >= 256 * DI_) return;
    int row = i / DI_, col = i - row * DI_;
    g_wpad[L][i] = (row < 80) ? rna_tf32(xw[((size_t)L * 80 + row) * DI_ + col]) : 0.0f;
}

__global__ void paddt_kernel(const float* __restrict__ dw, int L) {
    int i = blockIdx.x * 256 + threadIdx.x;
    if (i >= DI_ * 64) return;
    int row = i >> 6, col = i & 63;
    g_dtwpad[L][i] = (col < DTRANK) ? rna_tf32(dw[((size_t)L * DI_ + row) * DTRANK + col]) : 0.0f;
}

__global__ void conv_silu_kernel(const float* __restrict__ conv_w,
                                 const float* __restrict__ conv_b, int layer) {
    int i = blockIdx.x * blockDim.x + threadIdx.x;
    if (i >= S_LEN * DI_) return;
    int t = i / DI_, c = i - t * DI_;
    const float* w = conv_w + ((size_t)layer * DI_ + c) * K_CONV;
    float acc = conv_b[layer * DI_ + c];
#pragma unroll
    for (int k = 0; k < K_CONV; k++) {
        int tt = t - (K_CONV - 1) + k;
        if (tt >= 0) acc += w[k] * g_xz[(size_t)tt * 2 * DI_ + c];
    }
    g_xs[i] = rna_tf32(silu_f(acc));
}

// ---------------- chunked selective scan ----------------
__global__ __launch_bounds__(256)
void scan_p1(const float* __restrict__ A_log, const float* __restrict__ dt_b, int layer) {
    int n  = threadIdx.x & 15;
    int cl = threadIdx.x >> 4;
    int c  = blockIdx.x * 16 + cl;
    int j  = blockIdx.y;
    float Acn  = -expf(A_log[((size_t)layer * DI_ + c) * N_ST + n]);
    float bias = dt_b[layer * DI_ + c];
    float h = 0.0f, p = 1.0f;
    int t0 = j * CLEN;
    for (int t = t0; t < t0 + CLEN; t++) {
        float a   = g_dtl[(size_t)t * DI_ + c] + bias;
        float dtv = (a > 20.0f) ? a : log1pf(__expf(a));
        float xv  = g_xs[(size_t)t * DI_ + c];
        float Bv  = g_xdbl[(size_t)t * XDP + DTRANK + n];
        float Cv  = g_xdbl[(size_t)t * XDP + DTRANK + N_ST + n];
        float dA  = __expf(dtv * Acn);
        h = dA * h + dtv * Bv * xv;
        p *= dA;
        float v = h * Cv;
#pragma unroll
        for (int o = 8; o > 0; o >>= 1)
            v += __shfl_down_sync(0xffffffffu, v, o, 16);
        if (n == 0) {
            g_y[(size_t)t * DI_ + c] = v;
            g_dtl[(size_t)t * DI_ + c] = dtv;
        }
    }
    int idx = c * N_ST + n;
    g_P[j * GROUPS + idx] = p;
    g_H[j * GROUPS + idx] = h;
}

__global__ void scan_p2() {
    int idx = blockIdx.x * blockDim.x + threadIdx.x;
    if (idx >= GROUPS) return;
    float carry = 0.0f;
#pragma unroll
    for (int j = 0; j < NCHUNK; j++) {
        g_C0[j * GROUPS + idx] = carry;
        carry = g_H[j * GROUPS + idx] + g_P[j * GROUPS + idx] * carry;
    }
}

__global__ __launch_bounds__(256)
void scan_p3(const float* __restrict__ A_log, const float* __restrict__ Dp, int layer) {
    int n  = threadIdx.x & 15;
    int cl = threadIdx.x >> 4;
    int c  = blockIdx.x * 16 + cl;
    int j  = blockIdx.y;
    float Acn = -expf(A_log[((size_t)layer * DI_ + c) * N_ST + n]);
    float Dpc = Dp[layer * DI_ + c];
    float carry = g_C0[j * GROUPS + c * N_ST + n];
    float p = 1.0f;
    int t0 = j * CLEN;
    if (j > 0) {
        for (int t = t0; t < t0 + CLEN; t++) {
            float dtv = g_dtl[(size_t)t * DI_ + c];
            float Cv  = g_xdbl[(size_t)t * XDP + DTRANK + N_ST + n];
            p *= __expf(dtv * Acn);
            float v = Cv * p * carry;
#pragma unroll
            for (int o = 8; o > 0; o >>= 1)
                v += __shfl_down_sync(0xffffffffu, v, o, 16);
            if (n == 0) {
                float xv = g_xs[(size_t)t * DI_ + c];
                float z  = g_xz[(size_t)t * 2 * DI_ + DI_ + c];
                g_y[(size_t)t * DI_ + c] =
                    rna_tf32((g_y[(size_t)t * DI_ + c] + v + xv * Dpc) * silu_f(z));
            }
        }
    } else {
        if (n == 0) {
            for (int t = t0; t < t0 + CLEN; t++) {
                float xv = g_xs[(size_t)t * DI_ + c];
                float z  = g_xz[(size_t)t * 2 * DI_ + DI_ + c];
                g_y[(size_t)t * DI_ + c] =
                    rna_tf32((g_y[(size_t)t * DI_ + c] + xv * Dpc) * silu_f(z));
            }
        }
    }
}

__global__ __launch_bounds__(256)
void ln_kernel(const float* __restrict__ gam, const float* __restrict__ bet, int layer) {
    int l = blockIdx.x;
    __shared__ float rsum[8], rsq[8];
    float sum = 0.0f, sq = 0.0f;
    for (int d = threadIdx.x; d < D_MODEL; d += 256) {
        float v = g_x[(size_t)l * D_MODEL + d] + g_tmp[(size_t)l * D_MODEL + d];
        sum += v; sq += v * v;
    }
#pragma unroll
    for (int o = 16; o > 0; o >>= 1) {
        sum += __shfl_down_sync(0xffffffffu, sum, o);
        sq  += __shfl_down_sync(0xffffffffu, sq, o);
    }
    int wid = threadIdx.x >> 5;
    if ((threadIdx.x & 31) == 0) { rsum[wid] = sum; rsq[wid] = sq; }
    __syncthreads();
    if (threadIdx.x == 0) {
        float s = 0.0f, q = 0.0f;
#pragma unroll
        for (int w = 0; w < 8; w++) { s += rsum[w]; q += rsq[w]; }
        rsum[0] = s; rsq[0] = q;
    }
    __syncthreads();
    float mu  = rsum[0] / (float)D_MODEL;
    float var = rsq[0] / (float)D_MODEL - mu * mu;
    float rinv = rsqrtf(var + 1e-5f);
    for (int d = threadIdx.x; d < D_MODEL; d += 256) {
        float v = g_x[(size_t)l * D_MODEL + d] + g_tmp[(size_t)l * D_MODEL + d];
        g_x[(size_t)l * D_MODEL + d] = rna_tf32(
            (v - mu) * rinv * gam[layer * D_MODEL + d] + bet[layer * D_MODEL + d]);
    }
}

// ---------------- launch ----------------
extern "C" void kernel_launch(void* const* d_in, const int* in_sizes, int n_in,
                              void* d_out, int out_size) {
    const int*   tokens  = (const int*)  d_in[0];
    const float* emb     = (const float*)d_in[1];
    const float* in_w    = (const float*)d_in[2];
    const float* conv_w  = (const float*)d_in[3];
    const float* conv_b  = (const float*)d_in[4];
    const float* xproj_w = (const float*)d_in[5];
    const float* dt_w    = (const float*)d_in[6];
    const float* dt_b    = (const float*)d_in[7];
    const float* A_log   = (const float*)d_in[8];
    const float* Dp      = (const float*)d_in[9];
    const float* out_w   = (const float*)d_in[10];
    const float* ln_g    = (const float*)d_in[11];
    const float* ln_b    = (const float*)d_in[12];
    const float* head_w  = (const float*)d_in[13];
    float* out = (float*)d_out;

    static float *px = nullptr, *pxz, *pxs, *pxdbl, *pdtl, *py, *ptmp, *pwh;
    static float *pwpad[NL_], *pdtw[NL_], *pwbig[NL_], *pwout[NL_];
    static cudaStream_t s1;
    static cudaEvent_t evFork, evWh, evJoin;
    static cudaEvent_t evIn[NL_], evPP[NL_], evOw[NL_];
    if (!px) {
        cudaGetSymbolAddress((void**)&pxz,   g_xz);
        cudaGetSymbolAddress((void**)&pxs,   g_xs);
        cudaGetSymbolAddress((void**)&pxdbl, g_xdbl);
        cudaGetSymbolAddress((void**)&pdtl,  g_dtl);
        cudaGetSymbolAddress((void**)&py,    g_y);
        cudaGetSymbolAddress((void**)&ptmp,  g_tmp);
        cudaGetSymbolAddress((void**)&pwh,   g_wh);
        float* base;
        cudaGetSymbolAddress((void**)&base, g_wpad);
        for (int L = 0; L < NL_; L++) pwpad[L] = base + (size_t)L * 256 * DI_;
        cudaGetSymbolAddress((void**)&base, g_dtwpad);
        for (int L = 0; L < NL_; L++) pdtw[L] = base + (size_t)L * DI_ * 64;
        cudaGetSymbolAddress((void**)&base, g_wbig);
        for (int L = 0; L < NL_; L++) pwbig[L] = base + (size_t)L * 2 * DI_ * D_MODEL;
        cudaGetSymbolAddress((void**)&base, g_wout);
        for (int L = 0; L < NL_; L++) pwout[L] = base + (size_t)L * D_MODEL * DI_;
        cudaFuncSetAttribute(gemm_big,
                             cudaFuncAttributeMaxDynamicSharedMemorySize, SMEM_BIG);
        cudaFuncSetAttribute(gemm_small<false>,
                             cudaFuncAttributeMaxDynamicSharedMemorySize, SMEM_SMALL);
        cudaFuncSetAttribute(gemm_small<true>,
                             cudaFuncAttributeMaxDynamicSharedMemorySize, SMEM_SMALL);
        cudaStreamCreateWithFlags(&s1, cudaStreamNonBlocking);
        cudaEventCreateWithFlags(&evFork, cudaEventDisableTiming);
        cudaEventCreateWithFlags(&evWh,   cudaEventDisableTiming);
        cudaEventCreateWithFlags(&evJoin, cudaEventDisableTiming);
        for (int L = 0; L < NL_; L++) {
            cudaEventCreateWithFlags(&evIn[L], cudaEventDisableTiming);
            cudaEventCreateWithFlags(&evPP[L], cudaEventDisableTiming);
            cudaEventCreateWithFlags(&evOw[L], cudaEventDisableTiming);
        }
        cudaGetSymbolAddress((void**)&px, g_x);
    }

    cudaEventRecord(evFork, 0);
    cudaStreamWaitEvent(s1, evFork, 0);

    embed_kernel<<<(S_LEN * D_MODEL + 255) / 256, 256>>>(tokens, emb);          // idx 0

    roundcopy4<<<(2 * DI_ * D_MODEL / 4 + 255) / 256, 256, 0, s1>>>(            // idx 1
        (float4*)pwbig[0], (const float4*)in_w, 2 * DI_ * D_MODEL / 4);
    cudaEventRecord(evIn[0], s1);
    padw_kernel<<<(256 * DI_ + 255) / 256, 256, 0, s1>>>(xproj_w, 0);           // idx 2

    // in-proj L0 at launch index 3 (profiled)
    cudaStreamWaitEvent(0, evIn[0], 0);
    gemm_big<<<dim3(S_LEN / 128, 2 * DI_ / 128), 128, SMEM_BIG>>>(
        px, pwbig[0], pxz, D_MODEL, D_MODEL, D_MODEL, 2 * DI_);                 // idx 3

    paddt_kernel<<<(DI_ * 64 + 255) / 256, 256, 0, s1>>>(dt_w, 0);
    cudaEventRecord(evPP[0], s1);
    roundcopy4<<<(D_MODEL * DI_ / 4 + 255) / 256, 256, 0, s1>>>(
        (float4*)pwout[0], (const float4*)out_w, D_MODEL * DI_ / 4);
    cudaEventRecord(evOw[0], s1);
    roundcopy4<<<(2 * DI_ * D_MODEL / 4 + 255) / 256, 256, 0, s1>>>(
        (float4*)pwbig[1], (const float4*)(in_w + (size_t)2 * DI_ * D_MODEL),
        2 * DI_ * D_MODEL / 4);
    cudaEventRecord(evIn[1], s1);
    padw_kernel<<<(256 * DI_ + 255) / 256, 256, 0, s1>>>(xproj_w, 1);
    paddt_kernel<<<(DI_ * 64 + 255) / 256, 256, 0, s1>>>(dt_w, 1);
    cudaEventRecord(evPP[1], s1);
    roundcopy4<<<(D_MODEL * DI_ / 4 + 255) / 256, 256, 0, s1>>>(
        (float4*)pwout[1], (const float4*)(out_w + (size_t)D_MODEL * DI_),
        D_MODEL * DI_ / 4);
    cudaEventRecord(evOw[1], s1);
    roundcopy4<<<(VOCAB * D_MODEL / 4 + 255) / 256, 256, 0, s1>>>(
        (float4*)pwh, (const float4*)head_w, VOCAB * D_MODEL / 4);
    cudaEventRecord(evWh, s1);
    cudaEventRecord(evJoin, s1);

    for (int L = 0; L < NL_; L++) {
        if (L > 0) {
            cudaStreamWaitEvent(0, evIn[L], 0);
            gemm_big<<<dim3(S_LEN / 128, 2 * DI_ / 128), 128, SMEM_BIG>>>(
                px, pwbig[L], pxz, D_MODEL, D_MODEL, D_MODEL, 2 * DI_);
        }
        conv_silu_kernel<<<(S_LEN * DI_ + 255) / 256, 256>>>(conv_w, conv_b, L);

        cudaStreamWaitEvent(0, evPP[L], 0);
        gemm_small<true><<<dim3(S_LEN / 64, XDP / 64), 128, SMEM_SMALL>>>(
            pxs, pwpad[L], pxdbl, DI_, DI_, DI_, XDP);
        gemm_small<false><<<dim3(S_LEN / 64, DI_ / 64), 128, SMEM_SMALL>>>(
            pxdbl, pdtw[L], pdtl, 64, XDP, 64, DI_);

        scan_p1<<<dim3(DI_ / 16, NCHUNK), 256>>>(A_log, dt_b, L);
        scan_p2<<<(GROUPS + 255) / 256, 256>>>();
        scan_p3<<<dim3(DI_ / 16, NCHUNK), 256>>>(A_log, Dp, L);

        cudaStreamWaitEvent(0, evOw[L], 0);
        gemm_small<false><<<dim3(S_LEN / 64, D_MODEL / 64), 128, SMEM_SMALL>>>(
            py, pwout[L], ptmp, DI_, DI_, DI_, D_MODEL);

        ln_kernel<<<S_LEN, 256>>>(ln_g, ln_b, L);
    }

    cudaStreamWaitEvent(0, evWh, 0);
    cudaStreamWaitEvent(0, evJoin, 0);
    gemm_big<<<dim3(S_LEN / 128, VOCAB / 128), 128, SMEM_BIG>>>(
        px, pwh, out, D_MODEL, D_MODEL, D_MODEL, VOCAB);
}